// round 1
// baseline (speedup 1.0000x reference)
#include <cuda_runtime.h>
#include <cstdint>
#include <cstddef>

// ---------------------------------------------------------------------------
// Problem constants
// ---------------------------------------------------------------------------
#define NN   100000        // nodes
#define NE   100000        // edges
#define DIM  768
#define DIM2 1536
#define NT   5
#define LN_EPS 1e-5f

// GEMM tiling
#define BM 64
#define BN 64
#define BK 16
#define LDA 20             // BK + 4 padding -> conflict-free fragment loads

// ---------------------------------------------------------------------------
// Device scratch (static __device__ arrays: allocation-free per harness rules)
// ---------------------------------------------------------------------------
__device__ float g_agg[(size_t)NN * DIM];      // aggregated messages [N, D]
__device__ int   g_bucket[NT][NE];             // edge ids grouped by type
__device__ int   g_count[NT];

// ---------------------------------------------------------------------------
// Helpers
// ---------------------------------------------------------------------------
__device__ __forceinline__ unsigned f2tf(float x) {
    unsigned r;
    asm("cvt.rna.tf32.f32 %0, %1;" : "=r"(r) : "f"(x));
    return r;
}

__device__ __forceinline__ void mma8(float& c0, float& c1, float& c2, float& c3,
                                     unsigned a0, unsigned a1, unsigned a2, unsigned a3,
                                     unsigned b0, unsigned b1) {
    asm volatile(
        "mma.sync.aligned.m16n8k8.row.col.f32.tf32.tf32.f32 "
        "{%0,%1,%2,%3}, {%4,%5,%6,%7}, {%8,%9}, {%0,%1,%2,%3};\n"
        : "+f"(c0), "+f"(c1), "+f"(c2), "+f"(c3)
        : "r"(a0), "r"(a1), "r"(a2), "r"(a3), "r"(b0), "r"(b1));
}

// ---------------------------------------------------------------------------
// K0: zero the aggregation buffer + type counters
// ---------------------------------------------------------------------------
__global__ void k_init() {
    size_t idx = (size_t)blockIdx.x * blockDim.x + threadIdx.x;
    if (idx < NT) g_count[idx] = 0;
    float4* p = reinterpret_cast<float4*>(g_agg);
    size_t n4 = (size_t)NN * DIM / 4;
    size_t stride = (size_t)gridDim.x * blockDim.x;
    for (size_t i = idx; i < n4; i += stride) p[i] = make_float4(0.f, 0.f, 0.f, 0.f);
}

// ---------------------------------------------------------------------------
// K1: bucket edges by relation type
// ---------------------------------------------------------------------------
__global__ void k_bucket(const int* __restrict__ etype) {
    int e = blockIdx.x * blockDim.x + threadIdx.x;
    if (e < NE) {
        int t = etype[e];
        int pos = atomicAdd(&g_count[t], 1);
        g_bucket[t][pos] = e;
    }
}

// ---------------------------------------------------------------------------
// K2: per-type gather-GEMM  msg = X[src] @ W_msg[t]^T + b_msg[t],
//     scatter-add (atomic) into g_agg[tgt]
//     grid: (DIM/BN, ceil(NE/BM), NT), block: 128 (4 warps, 2x2 warp tile)
// ---------------------------------------------------------------------------
__global__ __launch_bounds__(128) void k_msg(const float* __restrict__ X,
                                             const float* __restrict__ Wm,
                                             const float* __restrict__ bm,
                                             const int*   __restrict__ eidx) {
    int t = blockIdx.z;
    int cnt = g_count[t];
    int m0 = blockIdx.y * BM;
    if (m0 >= cnt) return;
    int n0 = blockIdx.x * BN;

    __shared__ unsigned As[BM][LDA];
    __shared__ unsigned Bs[BN][LDA];
    __shared__ int s_src[BM];
    __shared__ int s_tgt[BM];

    int tid = threadIdx.x;
    if (tid < BM) {
        int slot = m0 + tid;
        if (slot < cnt) {
            int e = g_bucket[t][slot];
            s_src[tid] = eidx[e];
            s_tgt[tid] = eidx[NE + e];
        } else {
            s_src[tid] = 0;
            s_tgt[tid] = -1;
        }
    }
    __syncthreads();

    const float* Wt = Wm + (size_t)t * DIM * DIM;

    int lane = tid & 31;
    int warp = tid >> 5;
    int wm = warp >> 1, wn = warp & 1;
    int g = lane >> 2, tg = lane & 3;

    float c[2][4][4];
#pragma unroll
    for (int i = 0; i < 2; i++)
#pragma unroll
        for (int j = 0; j < 4; j++)
#pragma unroll
            for (int r = 0; r < 4; r++) c[i][j][r] = 0.f;

    for (int kt = 0; kt < DIM / BK; ++kt) {
        // ---- load A tile (gathered node features), convert to tf32 ----
#pragma unroll
        for (int j = 0; j < 2; ++j) {
            int lin = j * 128 + tid;
            int row = lin >> 2, q = lin & 3;
            const float4 v = *reinterpret_cast<const float4*>(
                X + (size_t)s_src[row] * DIM + kt * BK + q * 4);
            As[row][q * 4 + 0] = f2tf(v.x);
            As[row][q * 4 + 1] = f2tf(v.y);
            As[row][q * 4 + 2] = f2tf(v.z);
            As[row][q * 4 + 3] = f2tf(v.w);
        }
        // ---- load B tile (W_msg[t], row-major [out, in] -> K contiguous) ----
#pragma unroll
        for (int j = 0; j < 2; ++j) {
            int lin = j * 128 + tid;
            int row = lin >> 2, q = lin & 3;
            const float4 v = *reinterpret_cast<const float4*>(
                Wt + (size_t)(n0 + row) * DIM + kt * BK + q * 4);
            Bs[row][q * 4 + 0] = f2tf(v.x);
            Bs[row][q * 4 + 1] = f2tf(v.y);
            Bs[row][q * 4 + 2] = f2tf(v.z);
            Bs[row][q * 4 + 3] = f2tf(v.w);
        }
        __syncthreads();

#pragma unroll
        for (int ks = 0; ks < 2; ++ks) {
            int k0 = ks * 8;
            unsigned a[2][4], b[4][2];
#pragma unroll
            for (int im = 0; im < 2; ++im) {
                int mb = wm * 32 + im * 16;
                a[im][0] = As[mb + g][k0 + tg];
                a[im][1] = As[mb + g + 8][k0 + tg];
                a[im][2] = As[mb + g][k0 + tg + 4];
                a[im][3] = As[mb + g + 8][k0 + tg + 4];
            }
#pragma unroll
            for (int in_ = 0; in_ < 4; ++in_) {
                int nb = wn * 32 + in_ * 8 + g;
                b[in_][0] = Bs[nb][k0 + tg];
                b[in_][1] = Bs[nb][k0 + tg + 4];
            }
#pragma unroll
            for (int im = 0; im < 2; ++im)
#pragma unroll
                for (int in_ = 0; in_ < 4; ++in_)
                    mma8(c[im][in_][0], c[im][in_][1], c[im][in_][2], c[im][in_][3],
                         a[im][0], a[im][1], a[im][2], a[im][3],
                         b[in_][0], b[in_][1]);
        }
        __syncthreads();
    }

    // ---- epilogue: + bias, scatter-add to target node ----
#pragma unroll
    for (int im = 0; im < 2; ++im) {
#pragma unroll
        for (int r2 = 0; r2 < 2; ++r2) {
            int rloc = wm * 32 + im * 16 + g + r2 * 8;
            int tgt = s_tgt[rloc];
            if (tgt < 0) continue;
            float* dst = g_agg + (size_t)tgt * DIM;
#pragma unroll
            for (int in_ = 0; in_ < 4; ++in_) {
#pragma unroll
                for (int cc = 0; cc < 2; ++cc) {
                    int col = n0 + wn * 32 + in_ * 8 + tg * 2 + cc;
                    float v = c[im][in_][r2 * 2 + cc] + bm[t * DIM + col];
                    atomicAdd(dst + col, v);
                }
            }
        }
    }
}

// ---------------------------------------------------------------------------
// K3: update GEMM  y = x + relu([X | agg] @ W_upd^T + b_upd)   (pre-LN)
//     grid: (DIM/BN, ceil(NN/BM)), block: 128
// ---------------------------------------------------------------------------
__global__ __launch_bounds__(128) void k_upd(const float* __restrict__ X,
                                             const float* __restrict__ Wu,
                                             const float* __restrict__ bu,
                                             float* __restrict__ out) {
    int m0 = blockIdx.y * BM;
    int n0 = blockIdx.x * BN;

    __shared__ unsigned As[BM][LDA];
    __shared__ unsigned Bs[BN][LDA];

    int tid = threadIdx.x;
    int lane = tid & 31;
    int warp = tid >> 5;
    int wm = warp >> 1, wn = warp & 1;
    int g = lane >> 2, tg = lane & 3;

    float c[2][4][4];
#pragma unroll
    for (int i = 0; i < 2; i++)
#pragma unroll
        for (int j = 0; j < 4; j++)
#pragma unroll
            for (int r = 0; r < 4; r++) c[i][j][r] = 0.f;

    for (int kt = 0; kt < DIM2 / BK; ++kt) {
        int kk = kt * BK;
        // ---- load A tile: first 768 k from X, rest from g_agg ----
#pragma unroll
        for (int j = 0; j < 2; ++j) {
            int lin = j * 128 + tid;
            int row = lin >> 2, q = lin & 3;
            int node = m0 + row;
            if (node >= NN) node = NN - 1;
            const float* src = (kk < DIM)
                ? (X + (size_t)node * DIM + kk)
                : (g_agg + (size_t)node * DIM + (kk - DIM));
            const float4 v = *reinterpret_cast<const float4*>(src + q * 4);
            As[row][q * 4 + 0] = f2tf(v.x);
            As[row][q * 4 + 1] = f2tf(v.y);
            As[row][q * 4 + 2] = f2tf(v.z);
            As[row][q * 4 + 3] = f2tf(v.w);
        }
        // ---- load B tile (W_upd row-major [D, 2D]) ----
#pragma unroll
        for (int j = 0; j < 2; ++j) {
            int lin = j * 128 + tid;
            int row = lin >> 2, q = lin & 3;
            const float4 v = *reinterpret_cast<const float4*>(
                Wu + (size_t)(n0 + row) * DIM2 + kk + q * 4);
            Bs[row][q * 4 + 0] = f2tf(v.x);
            Bs[row][q * 4 + 1] = f2tf(v.y);
            Bs[row][q * 4 + 2] = f2tf(v.z);
            Bs[row][q * 4 + 3] = f2tf(v.w);
        }
        __syncthreads();

#pragma unroll
        for (int ks = 0; ks < 2; ++ks) {
            int k0 = ks * 8;
            unsigned a[2][4], b[4][2];
#pragma unroll
            for (int im = 0; im < 2; ++im) {
                int mb = wm * 32 + im * 16;
                a[im][0] = As[mb + g][k0 + tg];
                a[im][1] = As[mb + g + 8][k0 + tg];
                a[im][2] = As[mb + g][k0 + tg + 4];
                a[im][3] = As[mb + g + 8][k0 + tg + 4];
            }
#pragma unroll
            for (int in_ = 0; in_ < 4; ++in_) {
                int nb = wn * 32 + in_ * 8 + g;
                b[in_][0] = Bs[nb][k0 + tg];
                b[in_][1] = Bs[nb][k0 + tg + 4];
            }
#pragma unroll
            for (int im = 0; im < 2; ++im)
#pragma unroll
                for (int in_ = 0; in_ < 4; ++in_)
                    mma8(c[im][in_][0], c[im][in_][1], c[im][in_][2], c[im][in_][3],
                         a[im][0], a[im][1], a[im][2], a[im][3],
                         b[in_][0], b[in_][1]);
        }
        __syncthreads();
    }

    // ---- epilogue: bias, relu, residual add; write pre-LN y ----
#pragma unroll
    for (int im = 0; im < 2; ++im) {
#pragma unroll
        for (int r2 = 0; r2 < 2; ++r2) {
            int rloc = wm * 32 + im * 16 + g + r2 * 8;
            int node = m0 + rloc;
            if (node >= NN) continue;
#pragma unroll
            for (int in_ = 0; in_ < 4; ++in_) {
#pragma unroll
                for (int cc = 0; cc < 2; ++cc) {
                    int col = n0 + wn * 32 + in_ * 8 + tg * 2 + cc;
                    float v = c[im][in_][r2 * 2 + cc] + bu[col];
                    v = fmaxf(v, 0.f) + X[(size_t)node * DIM + col];
                    out[(size_t)node * DIM + col] = v;
                }
            }
        }
    }
}

// ---------------------------------------------------------------------------
// K4: in-place LayerNorm over each row of out
// ---------------------------------------------------------------------------
__global__ __launch_bounds__(256) void k_ln(float* __restrict__ out,
                                            const float* __restrict__ gamma,
                                            const float* __restrict__ beta) {
    __shared__ float red[34];
    int n = blockIdx.x;
    float* row = out + (size_t)n * DIM;
    int tid = threadIdx.x;

    float v0 = row[tid], v1 = row[tid + 256], v2 = row[tid + 512];
    float s = v0 + v1 + v2;
    float s2 = v0 * v0 + v1 * v1 + v2 * v2;
#pragma unroll
    for (int o = 16; o > 0; o >>= 1) {
        s  += __shfl_xor_sync(0xffffffffu, s, o);
        s2 += __shfl_xor_sync(0xffffffffu, s2, o);
    }
    int w = tid >> 5, l = tid & 31;
    if (l == 0) { red[w] = s; red[8 + w] = s2; }
    __syncthreads();
    if (w == 0) {
        float a = (l < 8) ? red[l] : 0.f;
        float b = (l < 8) ? red[8 + l] : 0.f;
#pragma unroll
        for (int o = 4; o > 0; o >>= 1) {
            a += __shfl_xor_sync(0xffffffffu, a, o);
            b += __shfl_xor_sync(0xffffffffu, b, o);
        }
        if (l == 0) { red[32] = a; red[33] = b; }
    }
    __syncthreads();
    float mu = red[32] * (1.0f / DIM);
    float var = red[33] * (1.0f / DIM) - mu * mu;
    float inv = rsqrtf(var + LN_EPS);
    row[tid]       = (v0 - mu) * inv * gamma[tid]       + beta[tid];
    row[tid + 256] = (v1 - mu) * inv * gamma[tid + 256] + beta[tid + 256];
    row[tid + 512] = (v2 - mu) * inv * gamma[tid + 512] + beta[tid + 512];
}

// ---------------------------------------------------------------------------
// kernel_launch
// ---------------------------------------------------------------------------
extern "C" void kernel_launch(void* const* d_in, const int* in_sizes, int n_in,
                              void* d_out, int out_size) {
    const float* X   = (const float*)d_in[0];  // node_features [N, D]
    const float* Wm  = (const float*)d_in[1];  // W_msg [T, D, D]
    const float* bm  = (const float*)d_in[2];  // b_msg [T, D]
    const float* Wu  = (const float*)d_in[3];  // W_upd [D, 2D]
    const float* bu  = (const float*)d_in[4];  // b_upd [D]
    const float* gam = (const float*)d_in[5];  // ln_gamma [D]
    const float* bet = (const float*)d_in[6];  // ln_beta [D]
    const int*   eidx= (const int*)d_in[7];    // edge_indices [2, E]
    const int*   etyp= (const int*)d_in[8];    // edge_types [E]
    float* out = (float*)d_out;

    (void)in_sizes; (void)n_in; (void)out_size;

    k_init<<<4096, 256>>>();
    k_bucket<<<(NE + 255) / 256, 256>>>(etyp);

    dim3 gm(DIM / BN, (NE + BM - 1) / BM, NT);
    k_msg<<<gm, 128>>>(X, Wm, bm, eidx);

    dim3 gu(DIM / BN, (NN + BM - 1) / BM);
    k_upd<<<gu, 128>>>(X, Wu, bu, out);

    k_ln<<<NN, 256>>>(out, gam, bet);
}

// round 2
// speedup vs baseline: 1.4675x; 1.4675x over previous
#include <cuda_runtime.h>
#include <cstdint>
#include <cstddef>

// ---------------------------------------------------------------------------
// Problem constants
// ---------------------------------------------------------------------------
#define NN   100000        // nodes
#define NE   100000        // edges
#define DIM  768
#define DIM2 1536
#define NT   5
#define LN_EPS 1e-5f

// GEMM tiling: 128x128 block tile, 4 warps, 64x64 warp tile, BK=16
#define BM 128
#define BN 128
#define BK 16
#define LDA 20             // BK + 4 padding -> conflict-free fragment LDS

// ---------------------------------------------------------------------------
// Device scratch (static __device__ arrays: allocation-free per harness rules)
// ---------------------------------------------------------------------------
__device__ float g_agg[(size_t)NN * DIM];      // aggregated messages [N, D]
__device__ int   g_bucket[NT][NE];             // edge ids grouped by type
__device__ int   g_count[NT];

// ---------------------------------------------------------------------------
// Helpers
// ---------------------------------------------------------------------------
__device__ __forceinline__ unsigned f2tf(float x) {
    unsigned r;
    asm("cvt.rna.tf32.f32 %0, %1;" : "=r"(r) : "f"(x));
    return r;
}

__device__ __forceinline__ void mma8(float& c0, float& c1, float& c2, float& c3,
                                     unsigned a0, unsigned a1, unsigned a2, unsigned a3,
                                     unsigned b0, unsigned b1) {
    asm volatile(
        "mma.sync.aligned.m16n8k8.row.col.f32.tf32.tf32.f32 "
        "{%0,%1,%2,%3}, {%4,%5,%6,%7}, {%8,%9}, {%0,%1,%2,%3};\n"
        : "+f"(c0), "+f"(c1), "+f"(c2), "+f"(c3)
        : "r"(a0), "r"(a1), "r"(a2), "r"(a3), "r"(b0), "r"(b1));
}

// Store a prefetched tile (4 float4 per thread) into a smem buffer with cvt.
__device__ __forceinline__ void sts_tile(unsigned (*S)[LDA], int tid, const float4* r) {
#pragma unroll
    for (int j = 0; j < 4; ++j) {
        int lin = j * 128 + tid;
        int row = lin >> 2, q = lin & 3;
        S[row][q * 4 + 0] = f2tf(r[j].x);
        S[row][q * 4 + 1] = f2tf(r[j].y);
        S[row][q * 4 + 2] = f2tf(r[j].z);
        S[row][q * 4 + 3] = f2tf(r[j].w);
    }
}

// One BK=16 slice of MMAs: 64x64 warp tile, 2 k-steps of m16n8k8.
__device__ __forceinline__ void compute_tile(const unsigned (*As)[LDA],
                                             const unsigned (*Bs)[LDA],
                                             float c[4][8][4],
                                             int wm, int wn, int g, int tg) {
#pragma unroll
    for (int ks = 0; ks < 2; ++ks) {
        int k0 = ks * 8;
        unsigned a[4][4], b[8][2];
#pragma unroll
        for (int im = 0; im < 4; ++im) {
            int mb = wm * 64 + im * 16;
            a[im][0] = As[mb + g][k0 + tg];
            a[im][1] = As[mb + g + 8][k0 + tg];
            a[im][2] = As[mb + g][k0 + tg + 4];
            a[im][3] = As[mb + g + 8][k0 + tg + 4];
        }
#pragma unroll
        for (int in_ = 0; in_ < 8; ++in_) {
            int nb = wn * 64 + in_ * 8 + g;
            b[in_][0] = Bs[nb][k0 + tg];
            b[in_][1] = Bs[nb][k0 + tg + 4];
        }
#pragma unroll
        for (int im = 0; im < 4; ++im)
#pragma unroll
            for (int in_ = 0; in_ < 8; ++in_)
                mma8(c[im][in_][0], c[im][in_][1], c[im][in_][2], c[im][in_][3],
                     a[im][0], a[im][1], a[im][2], a[im][3],
                     b[in_][0], b[in_][1]);
    }
}

// ---------------------------------------------------------------------------
// K0: zero the aggregation buffer + type counters
// ---------------------------------------------------------------------------
__global__ void k_init() {
    size_t idx = (size_t)blockIdx.x * blockDim.x + threadIdx.x;
    if (idx < NT) g_count[idx] = 0;
    float4* p = reinterpret_cast<float4*>(g_agg);
    size_t n4 = (size_t)NN * DIM / 4;
    size_t stride = (size_t)gridDim.x * blockDim.x;
    for (size_t i = idx; i < n4; i += stride) p[i] = make_float4(0.f, 0.f, 0.f, 0.f);
}

// ---------------------------------------------------------------------------
// K1: bucket edges by relation type
// ---------------------------------------------------------------------------
__global__ void k_bucket(const int* __restrict__ etype) {
    int e = blockIdx.x * blockDim.x + threadIdx.x;
    if (e < NE) {
        int t = etype[e];
        int pos = atomicAdd(&g_count[t], 1);
        g_bucket[t][pos] = e;
    }
}

// ---------------------------------------------------------------------------
// K2: per-type gather-GEMM  msg = X[src] @ W_msg[t]^T + b_msg[t],
//     scatter-add (atomic) into g_agg[tgt]
//     grid: (DIM/BN, ceil(NE/BM), NT), block: 128
// ---------------------------------------------------------------------------
__global__ __launch_bounds__(128) void k_msg(const float* __restrict__ X,
                                             const float* __restrict__ Wm,
                                             const float* __restrict__ bm,
                                             const int*   __restrict__ eidx) {
    int t = blockIdx.z;
    int cnt = g_count[t];
    int m0 = blockIdx.y * BM;
    if (m0 >= cnt) return;
    int n0 = blockIdx.x * BN;

    __shared__ unsigned As[2][BM][LDA];
    __shared__ unsigned Bs[2][BN][LDA];
    __shared__ int s_src[BM];
    __shared__ int s_tgt[BM];

    int tid = threadIdx.x;
    {
        int slot = m0 + tid;
        if (slot < cnt) {
            int e = g_bucket[t][slot];
            s_src[tid] = eidx[e];
            s_tgt[tid] = eidx[NE + e];
        } else {
            s_src[tid] = 0;
            s_tgt[tid] = -1;
        }
    }
    __syncthreads();

    const float* Wt = Wm + (size_t)t * DIM * DIM;

    int lane = tid & 31;
    int warp = tid >> 5;
    int wm = warp >> 1, wn = warp & 1;
    int g = lane >> 2, tg = lane & 3;

    float c[4][8][4];
#pragma unroll
    for (int i = 0; i < 4; i++)
#pragma unroll
        for (int j = 0; j < 8; j++)
#pragma unroll
            for (int r = 0; r < 4; r++) c[i][j][r] = 0.f;

    float4 ra[4], rb[4];

    // prefetch kt=0
#pragma unroll
    for (int j = 0; j < 4; ++j) {
        int lin = j * 128 + tid;
        int row = lin >> 2, q = lin & 3;
        ra[j] = *reinterpret_cast<const float4*>(X + (size_t)s_src[row] * DIM + q * 4);
        rb[j] = *reinterpret_cast<const float4*>(Wt + (size_t)(n0 + row) * DIM + q * 4);
    }
    sts_tile(As[0], tid, ra);
    sts_tile(Bs[0], tid, rb);
    __syncthreads();

    const int KT = DIM / BK;  // 48
    for (int kt = 0; kt < KT; ++kt) {
        int cur = kt & 1;
        if (kt + 1 < KT) {
            int kk = (kt + 1) * BK;
#pragma unroll
            for (int j = 0; j < 4; ++j) {
                int lin = j * 128 + tid;
                int row = lin >> 2, q = lin & 3;
                ra[j] = *reinterpret_cast<const float4*>(
                    X + (size_t)s_src[row] * DIM + kk + q * 4);
                rb[j] = *reinterpret_cast<const float4*>(
                    Wt + (size_t)(n0 + row) * DIM + kk + q * 4);
            }
        }
        compute_tile(As[cur], Bs[cur], c, wm, wn, g, tg);
        if (kt + 1 < KT) {
            sts_tile(As[cur ^ 1], tid, ra);
            sts_tile(Bs[cur ^ 1], tid, rb);
        }
        __syncthreads();
    }

    // ---- epilogue: + bias, scatter-add to target node ----
#pragma unroll
    for (int im = 0; im < 4; ++im) {
#pragma unroll
        for (int r2 = 0; r2 < 2; ++r2) {
            int rloc = wm * 64 + im * 16 + g + r2 * 8;
            int tgt = s_tgt[rloc];
            if (tgt < 0) continue;
            float* dst = g_agg + (size_t)tgt * DIM;
#pragma unroll
            for (int in_ = 0; in_ < 8; ++in_) {
#pragma unroll
                for (int cc = 0; cc < 2; ++cc) {
                    int col = n0 + wn * 64 + in_ * 8 + tg * 2 + cc;
                    float v = c[im][in_][r2 * 2 + cc] + bm[t * DIM + col];
                    atomicAdd(dst + col, v);
                }
            }
        }
    }
}

// ---------------------------------------------------------------------------
// K3: update GEMM  y = x + relu([X | agg] @ W_upd^T + b_upd)   (pre-LN)
//     grid: (DIM/BN, ceil(NN/BM)), block: 128
// ---------------------------------------------------------------------------
__global__ __launch_bounds__(128) void k_upd(const float* __restrict__ X,
                                             const float* __restrict__ Wu,
                                             const float* __restrict__ bu,
                                             float* __restrict__ out) {
    int m0 = blockIdx.y * BM;
    int n0 = blockIdx.x * BN;

    __shared__ unsigned As[2][BM][LDA];
    __shared__ unsigned Bs[2][BN][LDA];

    int tid = threadIdx.x;
    int lane = tid & 31;
    int warp = tid >> 5;
    int wm = warp >> 1, wn = warp & 1;
    int g = lane >> 2, tg = lane & 3;

    float c[4][8][4];
#pragma unroll
    for (int i = 0; i < 4; i++)
#pragma unroll
        for (int j = 0; j < 8; j++)
#pragma unroll
            for (int r = 0; r < 4; r++) c[i][j][r] = 0.f;

    float4 ra[4], rb[4];

    // prefetch kt=0 (kk=0 < DIM, so A comes from X)
#pragma unroll
    for (int j = 0; j < 4; ++j) {
        int lin = j * 128 + tid;
        int row = lin >> 2, q = lin & 3;
        int node = m0 + row; if (node >= NN) node = NN - 1;
        ra[j] = *reinterpret_cast<const float4*>(X + (size_t)node * DIM + q * 4);
        rb[j] = *reinterpret_cast<const float4*>(Wu + (size_t)(n0 + row) * DIM2 + q * 4);
    }
    sts_tile(As[0], tid, ra);
    sts_tile(Bs[0], tid, rb);
    __syncthreads();

    const int KT = DIM2 / BK;  // 96
    for (int kt = 0; kt < KT; ++kt) {
        int cur = kt & 1;
        if (kt + 1 < KT) {
            int kk = (kt + 1) * BK;
#pragma unroll
            for (int j = 0; j < 4; ++j) {
                int lin = j * 128 + tid;
                int row = lin >> 2, q = lin & 3;
                int node = m0 + row; if (node >= NN) node = NN - 1;
                const float* src = (kk < DIM)
                    ? (X + (size_t)node * DIM + kk)
                    : (g_agg + (size_t)node * DIM + (kk - DIM));
                ra[j] = *reinterpret_cast<const float4*>(src + q * 4);
                rb[j] = *reinterpret_cast<const float4*>(
                    Wu + (size_t)(n0 + row) * DIM2 + kk + q * 4);
            }
        }
        compute_tile(As[cur], Bs[cur], c, wm, wn, g, tg);
        if (kt + 1 < KT) {
            sts_tile(As[cur ^ 1], tid, ra);
            sts_tile(Bs[cur ^ 1], tid, rb);
        }
        __syncthreads();
    }

    // ---- epilogue: bias, relu, residual add; write pre-LN y (float2) ----
#pragma unroll
    for (int im = 0; im < 4; ++im) {
#pragma unroll
        for (int r2 = 0; r2 < 2; ++r2) {
            int rloc = wm * 64 + im * 16 + g + r2 * 8;
            int node = m0 + rloc;
            if (node >= NN) continue;
#pragma unroll
            for (int in_ = 0; in_ < 8; ++in_) {
                int col = n0 + wn * 64 + in_ * 8 + tg * 2;
                float2 xres = *reinterpret_cast<const float2*>(
                    X + (size_t)node * DIM + col);
                float v0 = c[im][in_][r2 * 2 + 0] + bu[col];
                float v1 = c[im][in_][r2 * 2 + 1] + bu[col + 1];
                float2 o;
                o.x = fmaxf(v0, 0.f) + xres.x;
                o.y = fmaxf(v1, 0.f) + xres.y;
                *reinterpret_cast<float2*>(out + (size_t)node * DIM + col) = o;
            }
        }
    }
}

// ---------------------------------------------------------------------------
// K4: in-place LayerNorm over each row of out
// ---------------------------------------------------------------------------
__global__ __launch_bounds__(256) void k_ln(float* __restrict__ out,
                                            const float* __restrict__ gamma,
                                            const float* __restrict__ beta) {
    __shared__ float red[34];
    int n = blockIdx.x;
    float* row = out + (size_t)n * DIM;
    int tid = threadIdx.x;

    float v0 = row[tid], v1 = row[tid + 256], v2 = row[tid + 512];
    float s = v0 + v1 + v2;
    float s2 = v0 * v0 + v1 * v1 + v2 * v2;
#pragma unroll
    for (int o = 16; o > 0; o >>= 1) {
        s  += __shfl_xor_sync(0xffffffffu, s, o);
        s2 += __shfl_xor_sync(0xffffffffu, s2, o);
    }
    int w = tid >> 5, l = tid & 31;
    if (l == 0) { red[w] = s; red[8 + w] = s2; }
    __syncthreads();
    if (w == 0) {
        float a = (l < 8) ? red[l] : 0.f;
        float b = (l < 8) ? red[8 + l] : 0.f;
#pragma unroll
        for (int o = 4; o > 0; o >>= 1) {
            a += __shfl_xor_sync(0xffffffffu, a, o);
            b += __shfl_xor_sync(0xffffffffu, b, o);
        }
        if (l == 0) { red[32] = a; red[33] = b; }
    }
    __syncthreads();
    float mu = red[32] * (1.0f / DIM);
    float var = red[33] * (1.0f / DIM) - mu * mu;
    float inv = rsqrtf(var + LN_EPS);
    row[tid]       = (v0 - mu) * inv * gamma[tid]       + beta[tid];
    row[tid + 256] = (v1 - mu) * inv * gamma[tid + 256] + beta[tid + 256];
    row[tid + 512] = (v2 - mu) * inv * gamma[tid + 512] + beta[tid + 512];
}

// ---------------------------------------------------------------------------
// kernel_launch
// ---------------------------------------------------------------------------
extern "C" void kernel_launch(void* const* d_in, const int* in_sizes, int n_in,
                              void* d_out, int out_size) {
    const float* X   = (const float*)d_in[0];  // node_features [N, D]
    const float* Wm  = (const float*)d_in[1];  // W_msg [T, D, D]
    const float* bm  = (const float*)d_in[2];  // b_msg [T, D]
    const float* Wu  = (const float*)d_in[3];  // W_upd [D, 2D]
    const float* bu  = (const float*)d_in[4];  // b_upd [D]
    const float* gam = (const float*)d_in[5];  // ln_gamma [D]
    const float* bet = (const float*)d_in[6];  // ln_beta [D]
    const int*   eidx= (const int*)d_in[7];    // edge_indices [2, E]
    const int*   etyp= (const int*)d_in[8];    // edge_types [E]
    float* out = (float*)d_out;

    (void)in_sizes; (void)n_in; (void)out_size;

    k_init<<<4096, 256>>>();
    k_bucket<<<(NE + 255) / 256, 256>>>(etyp);

    dim3 gm(DIM / BN, (NE + BM - 1) / BM, NT);
    k_msg<<<gm, 128>>>(X, Wm, bm, eidx);

    dim3 gu(DIM / BN, (NN + BM - 1) / BM);
    k_upd<<<gu, 128>>>(X, Wu, bu, out);

    k_ln<<<NN, 256>>>(out, gam, bet);
}

// round 5
// speedup vs baseline: 1.5746x; 1.0730x over previous
#include <cuda_runtime.h>
#include <cstdint>
#include <cstddef>

// ---------------------------------------------------------------------------
// Problem constants
// ---------------------------------------------------------------------------
#define NN   100000
#define NE   100000
#define DIM  768
#define DIM2 1536
#define NT   5
#define LN_EPS 1e-5f

// Tiling: CTA tile 128x256, 8 warps in 2x4, warp tile 64x64, BK=32, 3 stages
#define BM 128
#define BN 256
#define BK 32
#define NSTG 3
#define THREADS 256
#define LDA 36                  // floats per row (32 + 4 pad)
#define A_STG_BYTES (BM * LDA * 4)          // 18432
#define B_STG_BYTES (BN * LDA * 4)          // 36864
#define STG_BYTES   (A_STG_BYTES + B_STG_BYTES)  // 55296
#define SM_IDX   0              // 1024 bytes: s_src(512) + s_tgt(512)
#define SM_TILES 1024
#define SMEM_SZ  (SM_TILES + NSTG * STG_BYTES)   // 166912

// ---------------------------------------------------------------------------
// Device scratch
// ---------------------------------------------------------------------------
__device__ float g_agg[(size_t)NN * DIM];
__device__ int   g_bucket[NT][NE];
__device__ int   g_count[NT];

// ---------------------------------------------------------------------------
// Helpers
// ---------------------------------------------------------------------------
__device__ __forceinline__ uint32_t smem_u32(const void* p) {
    uint32_t a;
    asm("{ .reg .u64 t; cvta.to.shared.u64 t, %1; cvt.u32.u64 %0, t; }"
        : "=r"(a) : "l"(p));
    return a;
}

__device__ __forceinline__ void cpa16(uint32_t s, const void* g) {
    asm volatile("cp.async.cg.shared.global [%0], [%1], 16;"
                 :: "r"(s), "l"(g) : "memory");
}
__device__ __forceinline__ void cpa_commit() {
    asm volatile("cp.async.commit_group;" ::: "memory");
}
__device__ __forceinline__ void cpa_wait1() {
    asm volatile("cp.async.wait_group 1;" ::: "memory");
}

__device__ __forceinline__ unsigned f2tf(float x) {
    unsigned r;
    asm("cvt.rna.tf32.f32 %0, %1;" : "=r"(r) : "f"(x));
    return r;
}

__device__ __forceinline__ void mma8(float& c0, float& c1, float& c2, float& c3,
                                     unsigned a0, unsigned a1, unsigned a2, unsigned a3,
                                     unsigned b0, unsigned b1) {
    asm volatile(
        "mma.sync.aligned.m16n8k8.row.col.f32.tf32.tf32.f32 "
        "{%0,%1,%2,%3}, {%4,%5,%6,%7}, {%8,%9}, {%0,%1,%2,%3};\n"
        : "+f"(c0), "+f"(c1), "+f"(c2), "+f"(c3)
        : "r"(a0), "r"(a1), "r"(a2), "r"(a3), "r"(b0), "r"(b1));
}

// one BK=32 slice: 4 k-steps of m16n8k8 on a 64x64 warp tile.
// Fragments converted to tf32 with round-to-nearest at load (unbiased).
__device__ __forceinline__ void compute_stage(const float* __restrict__ As,
                                              const float* __restrict__ Bs,
                                              float c[4][8][4],
                                              int wm, int wn, int g, int tg) {
#pragma unroll
    for (int ks = 0; ks < 4; ++ks) {
        int k0 = ks * 8;
        unsigned a[4][4], b[8][2];
#pragma unroll
        for (int im = 0; im < 4; ++im) {
            int mb = wm * 64 + im * 16;
            a[im][0] = f2tf(As[(mb + g) * LDA + k0 + tg]);
            a[im][1] = f2tf(As[(mb + g + 8) * LDA + k0 + tg]);
            a[im][2] = f2tf(As[(mb + g) * LDA + k0 + tg + 4]);
            a[im][3] = f2tf(As[(mb + g + 8) * LDA + k0 + tg + 4]);
        }
#pragma unroll
        for (int in_ = 0; in_ < 8; ++in_) {
            int nb = wn * 64 + in_ * 8 + g;
            b[in_][0] = f2tf(Bs[nb * LDA + k0 + tg]);
            b[in_][1] = f2tf(Bs[nb * LDA + k0 + tg + 4]);
        }
#pragma unroll
        for (int im = 0; im < 4; ++im)
#pragma unroll
            for (int in_ = 0; in_ < 8; ++in_)
                mma8(c[im][in_][0], c[im][in_][1], c[im][in_][2], c[im][in_][3],
                     a[im][0], a[im][1], a[im][2], a[im][3],
                     b[in_][0], b[in_][1]);
    }
}

// ---------------------------------------------------------------------------
// K0 / K1: init + bucket
// ---------------------------------------------------------------------------
__global__ void k_init() {
    size_t idx = (size_t)blockIdx.x * blockDim.x + threadIdx.x;
    if (idx < NT) g_count[idx] = 0;
    float4* p = reinterpret_cast<float4*>(g_agg);
    size_t n4 = (size_t)NN * DIM / 4;
    size_t stride = (size_t)gridDim.x * blockDim.x;
    for (size_t i = idx; i < n4; i += stride) p[i] = make_float4(0.f, 0.f, 0.f, 0.f);
}

__global__ void k_bucket(const int* __restrict__ etype) {
    int e = blockIdx.x * blockDim.x + threadIdx.x;
    if (e < NE) {
        int t = etype[e];
        int pos = atomicAdd(&g_count[t], 1);
        g_bucket[t][pos] = e;
    }
}

// ---------------------------------------------------------------------------
// K2: per-type gather-GEMM, atomic scatter-add into g_agg
//     grid (DIM/BN, ceil(NE/BM), NT), 256 threads
// ---------------------------------------------------------------------------
__global__ __launch_bounds__(THREADS) void k_msg(const float* __restrict__ X,
                                                 const float* __restrict__ Wm,
                                                 const float* __restrict__ bm,
                                                 const int*   __restrict__ eidx) {
    int t = blockIdx.z;
    int cnt = g_count[t];
    int m0 = blockIdx.y * BM;
    if (m0 >= cnt) return;
    int n0 = blockIdx.x * BN;

    extern __shared__ char smem[];
    uint32_t sb = smem_u32(smem);
    int* s_src = (int*)(smem + SM_IDX);
    int* s_tgt = (int*)(smem + SM_IDX + 512);

    int tid = threadIdx.x, lane = tid & 31, w = tid >> 5;
    int wm = w >> 2, wn = w & 3;
    int g = lane >> 2, tg = lane & 3;

    if (tid < BM) {
        int slot = m0 + tid;
        if (slot < cnt) {
            int e = g_bucket[t][slot];
            s_src[tid] = eidx[e];
            s_tgt[tid] = eidx[NE + e];
        } else {
            s_src[tid] = 0;
            s_tgt[tid] = -1;
        }
    }
    __syncthreads();

    const float* Wt = Wm + (size_t)t * DIM * DIM;

    // tile fill via cp.async: A = 128 rows x 8 chunks (1024), B = 256 x 8 (2048)
    auto fill = [&](int stg, int kk) {
        uint32_t ab = sb + SM_TILES + stg * STG_BYTES;
        uint32_t bbs = ab + A_STG_BYTES;
#pragma unroll
        for (int p = 0; p < 4; ++p) {
            int f = p * THREADS + tid;
            int row = f >> 3, q = f & 7;
            cpa16(ab + row * (LDA * 4) + q * 16,
                  X + (size_t)s_src[row] * DIM + kk + q * 4);
        }
#pragma unroll
        for (int p = 0; p < 8; ++p) {
            int f = p * THREADS + tid;
            int row = f >> 3, q = f & 7;
            cpa16(bbs + row * (LDA * 4) + q * 16,
                  Wt + (size_t)(n0 + row) * DIM + kk + q * 4);
        }
    };

    float c[4][8][4];
#pragma unroll
    for (int i = 0; i < 4; i++)
#pragma unroll
        for (int j = 0; j < 8; j++)
#pragma unroll
            for (int r = 0; r < 4; r++) c[i][j][r] = 0.f;

    const int KT = DIM / BK;   // 24
    fill(0, 0); cpa_commit();
    fill(1, BK); cpa_commit();

    for (int kt = 0; kt < KT; ++kt) {
        cpa_wait1();
        __syncthreads();
        if (kt + 2 < KT) fill((kt + 2) % NSTG, (kt + 2) * BK);
        cpa_commit();
        const float* As = (const float*)(smem + SM_TILES + (kt % NSTG) * STG_BYTES);
        const float* Bs = As + BM * LDA;
        compute_stage(As, Bs, c, wm, wn, g, tg);
    }

    // epilogue: + bias, atomic scatter-add to target nodes
#pragma unroll
    for (int im = 0; im < 4; ++im) {
#pragma unroll
        for (int r2 = 0; r2 < 2; ++r2) {
            int rloc = wm * 64 + im * 16 + g + r2 * 8;
            int tgt = s_tgt[rloc];
            if (tgt < 0) continue;
            float* dst = g_agg + (size_t)tgt * DIM;
#pragma unroll
            for (int in_ = 0; in_ < 8; ++in_) {
                int col = n0 + wn * 64 + in_ * 8 + tg * 2;
                atomicAdd(dst + col,     c[im][in_][r2 * 2 + 0] + bm[t * DIM + col]);
                atomicAdd(dst + col + 1, c[im][in_][r2 * 2 + 1] + bm[t * DIM + col + 1]);
            }
        }
    }
}

// ---------------------------------------------------------------------------
// K3: update GEMM  out = relu([X | agg] @ W_upd^T + b_upd)  (residual in k_ln)
//     grid (DIM/BN, ceil(NN/BM)), 256 threads
// ---------------------------------------------------------------------------
__global__ __launch_bounds__(THREADS) void k_upd(const float* __restrict__ X,
                                                 const float* __restrict__ Wu,
                                                 const float* __restrict__ bu,
                                                 float* __restrict__ out) {
    int m0 = blockIdx.y * BM;
    int n0 = blockIdx.x * BN;

    extern __shared__ char smem[];
    uint32_t sb = smem_u32(smem);

    int tid = threadIdx.x, lane = tid & 31, w = tid >> 5;
    int wm = w >> 2, wn = w & 3;
    int g = lane >> 2, tg = lane & 3;

    auto fill = [&](int stg, int kk) {
        uint32_t ab = sb + SM_TILES + stg * STG_BYTES;
        uint32_t bbs = ab + A_STG_BYTES;
        const float* abase = (kk < DIM) ? X + kk : g_agg + (kk - DIM);
#pragma unroll
        for (int p = 0; p < 4; ++p) {
            int f = p * THREADS + tid;
            int row = f >> 3, q = f & 7;
            int node = m0 + row; if (node >= NN) node = NN - 1;
            cpa16(ab + row * (LDA * 4) + q * 16, abase + (size_t)node * DIM + q * 4);
        }
#pragma unroll
        for (int p = 0; p < 8; ++p) {
            int f = p * THREADS + tid;
            int row = f >> 3, q = f & 7;
            cpa16(bbs + row * (LDA * 4) + q * 16,
                  Wu + (size_t)(n0 + row) * DIM2 + kk + q * 4);
        }
    };

    float c[4][8][4];
#pragma unroll
    for (int i = 0; i < 4; i++)
#pragma unroll
        for (int j = 0; j < 8; j++)
#pragma unroll
            for (int r = 0; r < 4; r++) c[i][j][r] = 0.f;

    const int KT = DIM2 / BK;  // 48
    fill(0, 0); cpa_commit();
    fill(1, BK); cpa_commit();

    for (int kt = 0; kt < KT; ++kt) {
        cpa_wait1();
        __syncthreads();
        if (kt + 2 < KT) fill((kt + 2) % NSTG, (kt + 2) * BK);
        cpa_commit();
        const float* As = (const float*)(smem + SM_TILES + (kt % NSTG) * STG_BYTES);
        const float* Bs = As + BM * LDA;
        compute_stage(As, Bs, c, wm, wn, g, tg);
    }

    // epilogue: bias + relu, float2 stores
#pragma unroll
    for (int im = 0; im < 4; ++im) {
#pragma unroll
        for (int r2 = 0; r2 < 2; ++r2) {
            int rloc = wm * 64 + im * 16 + g + r2 * 8;
            int node = m0 + rloc;
            if (node >= NN) continue;
#pragma unroll
            for (int in_ = 0; in_ < 8; ++in_) {
                int col = n0 + wn * 64 + in_ * 8 + tg * 2;
                float2 o;
                o.x = fmaxf(c[im][in_][r2 * 2 + 0] + bu[col],     0.f);
                o.y = fmaxf(c[im][in_][r2 * 2 + 1] + bu[col + 1], 0.f);
                *reinterpret_cast<float2*>(out + (size_t)node * DIM + col) = o;
            }
        }
    }
}

// ---------------------------------------------------------------------------
// K4: out = LayerNorm(X + out) — residual folded in (coalesced X read)
// ---------------------------------------------------------------------------
__global__ __launch_bounds__(256) void k_ln(float* __restrict__ out,
                                            const float* __restrict__ X,
                                            const float* __restrict__ gamma,
                                            const float* __restrict__ beta) {
    __shared__ float red[34];
    int n = blockIdx.x;
    float* row = out + (size_t)n * DIM;
    const float* xr = X + (size_t)n * DIM;
    int tid = threadIdx.x;

    float v0 = row[tid]       + xr[tid];
    float v1 = row[tid + 256] + xr[tid + 256];
    float v2 = row[tid + 512] + xr[tid + 512];
    float s = v0 + v1 + v2;
    float s2 = v0 * v0 + v1 * v1 + v2 * v2;
#pragma unroll
    for (int o = 16; o > 0; o >>= 1) {
        s  += __shfl_xor_sync(0xffffffffu, s, o);
        s2 += __shfl_xor_sync(0xffffffffu, s2, o);
    }
    int w = tid >> 5, l = tid & 31;
    if (l == 0) { red[w] = s; red[8 + w] = s2; }
    __syncthreads();
    if (w == 0) {
        float a = (l < 8) ? red[l] : 0.f;
        float b = (l < 8) ? red[8 + l] : 0.f;
#pragma unroll
        for (int o = 4; o > 0; o >>= 1) {
            a += __shfl_xor_sync(0xffffffffu, a, o);
            b += __shfl_xor_sync(0xffffffffu, b, o);
        }
        if (l == 0) { red[32] = a; red[33] = b; }
    }
    __syncthreads();
    float mu = red[32] * (1.0f / DIM);
    float var = red[33] * (1.0f / DIM) - mu * mu;
    float inv = rsqrtf(var + LN_EPS);
    row[tid]       = (v0 - mu) * inv * gamma[tid]       + beta[tid];
    row[tid + 256] = (v1 - mu) * inv * gamma[tid + 256] + beta[tid + 256];
    row[tid + 512] = (v2 - mu) * inv * gamma[tid + 512] + beta[tid + 512];
}

// ---------------------------------------------------------------------------
// kernel_launch
// ---------------------------------------------------------------------------
extern "C" void kernel_launch(void* const* d_in, const int* in_sizes, int n_in,
                              void* d_out, int out_size) {
    const float* X   = (const float*)d_in[0];
    const float* Wm  = (const float*)d_in[1];
    const float* bm  = (const float*)d_in[2];
    const float* Wu  = (const float*)d_in[3];
    const float* bu  = (const float*)d_in[4];
    const float* gam = (const float*)d_in[5];
    const float* bet = (const float*)d_in[6];
    const int*   eidx= (const int*)d_in[7];
    const int*   etyp= (const int*)d_in[8];
    float* out = (float*)d_out;

    (void)in_sizes; (void)n_in; (void)out_size;

    cudaFuncSetAttribute(k_msg, cudaFuncAttributeMaxDynamicSharedMemorySize, SMEM_SZ);
    cudaFuncSetAttribute(k_upd, cudaFuncAttributeMaxDynamicSharedMemorySize, SMEM_SZ);

    k_init<<<4096, 256>>>();
    k_bucket<<<(NE + 255) / 256, 256>>>(etyp);

    dim3 gm(DIM / BN, (NE + BM - 1) / BM, NT);
    k_msg<<<gm, THREADS, SMEM_SZ>>>(X, Wm, bm, eidx);

    dim3 gu(DIM / BN, (NN + BM - 1) / BM);
    k_upd<<<gu, THREADS, SMEM_SZ>>>(X, Wu, bu, out);

    k_ln<<<NN, 256>>>(out, X, gam, bet);
}

// round 6
// speedup vs baseline: 1.7945x; 1.1396x over previous
#include <cuda_runtime.h>
#include <cstdint>
#include <cstddef>

// ---------------------------------------------------------------------------
// Problem constants
// ---------------------------------------------------------------------------
#define NN   100000
#define NE   100000
#define DIM  768
#define DIM2 1536
#define NT   5
#define LN_EPS 1e-5f

// Tiling: CTA tile 128x128, 4 warps in 2x2, warp tile 64x64, BK=32, 3 stages
// smem/CTA = 109KB -> 2 CTAs/SM (barrier/wait overlap across CTAs)
#define BM 128
#define BN 128
#define BK 32
#define NSTG 3
#define THREADS 128
#define LDA 36                  // floats per row (32 + 4 pad)
#define A_STG_BYTES (BM * LDA * 4)          // 18432
#define B_STG_BYTES (BN * LDA * 4)          // 18432
#define STG_BYTES   (A_STG_BYTES + B_STG_BYTES)  // 36864
#define SM_IDX   0              // 1024 bytes: s_src(512) + s_tgt(512)
#define SM_TILES 1024
#define SMEM_SZ  (SM_TILES + NSTG * STG_BYTES)   // 111616

// ---------------------------------------------------------------------------
// Device scratch (allocation-free per harness rules)
// ---------------------------------------------------------------------------
__device__ float g_agg[(size_t)NN * DIM];      // aggregated messages (f32 -> tf32 in place)
__device__ float g_xtf[(size_t)NN * DIM];      // tf32-rounded node features
__device__ float g_wmtf[(size_t)NT * DIM * DIM];   // tf32-rounded W_msg
__device__ float g_wutf[(size_t)DIM * DIM2];       // tf32-rounded W_upd
__device__ int   g_bucket[NT][NE];
__device__ int   g_count[NT];

// ---------------------------------------------------------------------------
// Helpers
// ---------------------------------------------------------------------------
__device__ __forceinline__ uint32_t smem_u32(const void* p) {
    uint32_t a;
    asm("{ .reg .u64 t; cvta.to.shared.u64 t, %1; cvt.u32.u64 %0, t; }"
        : "=r"(a) : "l"(p));
    return a;
}

__device__ __forceinline__ void cpa16(uint32_t s, const void* g) {
    asm volatile("cp.async.cg.shared.global [%0], [%1], 16;"
                 :: "r"(s), "l"(g) : "memory");
}
__device__ __forceinline__ void cpa_commit() {
    asm volatile("cp.async.commit_group;" ::: "memory");
}
__device__ __forceinline__ void cpa_wait1() {
    asm volatile("cp.async.wait_group 1;" ::: "memory");
}

__device__ __forceinline__ float f2tf_f(float x) {
    unsigned r;
    asm("cvt.rna.tf32.f32 %0, %1;" : "=r"(r) : "f"(x));
    return __uint_as_float(r);
}

__device__ __forceinline__ void mma8(float& c0, float& c1, float& c2, float& c3,
                                     unsigned a0, unsigned a1, unsigned a2, unsigned a3,
                                     unsigned b0, unsigned b1) {
    asm volatile(
        "mma.sync.aligned.m16n8k8.row.col.f32.tf32.tf32.f32 "
        "{%0,%1,%2,%3}, {%4,%5,%6,%7}, {%8,%9}, {%0,%1,%2,%3};\n"
        : "+f"(c0), "+f"(c1), "+f"(c2), "+f"(c3)
        : "r"(a0), "r"(a1), "r"(a2), "r"(a3), "r"(b0), "r"(b1));
}

// one BK=32 slice: 4 k-steps of m16n8k8 on a 64x64 warp tile.
// Operands are pre-rounded tf32 bits: no cvt in the hot loop.
__device__ __forceinline__ void compute_stage(const unsigned* __restrict__ As,
                                              const unsigned* __restrict__ Bs,
                                              float c[4][8][4],
                                              int wm, int wn, int g, int tg) {
#pragma unroll
    for (int ks = 0; ks < 4; ++ks) {
        int k0 = ks * 8;
        unsigned a[4][4], b[8][2];
#pragma unroll
        for (int im = 0; im < 4; ++im) {
            int mb = wm * 64 + im * 16;
            a[im][0] = As[(mb + g) * LDA + k0 + tg];
            a[im][1] = As[(mb + g + 8) * LDA + k0 + tg];
            a[im][2] = As[(mb + g) * LDA + k0 + tg + 4];
            a[im][3] = As[(mb + g + 8) * LDA + k0 + tg + 4];
        }
#pragma unroll
        for (int in_ = 0; in_ < 8; ++in_) {
            int nb = wn * 64 + in_ * 8 + g;
            b[in_][0] = Bs[nb * LDA + k0 + tg];
            b[in_][1] = Bs[nb * LDA + k0 + tg + 4];
        }
#pragma unroll
        for (int im = 0; im < 4; ++im)
#pragma unroll
            for (int in_ = 0; in_ < 8; ++in_)
                mma8(c[im][in_][0], c[im][in_][1], c[im][in_][2], c[im][in_][3],
                     a[im][0], a[im][1], a[im][2], a[im][3],
                     b[in_][0], b[in_][1]);
    }
}

// ---------------------------------------------------------------------------
// K0 / K1: init + bucket + tf32 convert
// ---------------------------------------------------------------------------
__global__ void k_init() {
    size_t idx = (size_t)blockIdx.x * blockDim.x + threadIdx.x;
    if (idx < NT) g_count[idx] = 0;
    float4* p = reinterpret_cast<float4*>(g_agg);
    size_t n4 = (size_t)NN * DIM / 4;
    size_t stride = (size_t)gridDim.x * blockDim.x;
    for (size_t i = idx; i < n4; i += stride) p[i] = make_float4(0.f, 0.f, 0.f, 0.f);
}

__global__ void k_bucket(const int* __restrict__ etype) {
    int e = blockIdx.x * blockDim.x + threadIdx.x;
    if (e < NE) {
        int t = etype[e];
        int pos = atomicAdd(&g_count[t], 1);
        g_bucket[t][pos] = e;
    }
}

// round-to-nearest tf32 copy (src may equal dst for in-place)
__global__ void k_cvt(const float* __restrict__ src, float* __restrict__ dst,
                      size_t n4) {
    size_t idx = (size_t)blockIdx.x * blockDim.x + threadIdx.x;
    size_t stride = (size_t)gridDim.x * blockDim.x;
    for (size_t i = idx; i < n4; i += stride) {
        float4 v = reinterpret_cast<const float4*>(src)[i];
        v.x = f2tf_f(v.x); v.y = f2tf_f(v.y);
        v.z = f2tf_f(v.z); v.w = f2tf_f(v.w);
        reinterpret_cast<float4*>(dst)[i] = v;
    }
}

// ---------------------------------------------------------------------------
// K2: per-type gather-GEMM, atomic scatter-add into g_agg
//     grid (DIM/BN, ceil(NE/BM), NT), 128 threads, 2 CTA/SM
// ---------------------------------------------------------------------------
__global__ __launch_bounds__(THREADS, 2) void k_msg(const float* __restrict__ bm,
                                                    const int*   __restrict__ eidx) {
    int t = blockIdx.z;
    int cnt = g_count[t];
    int m0 = blockIdx.y * BM;
    if (m0 >= cnt) return;
    int n0 = blockIdx.x * BN;

    extern __shared__ char smem[];
    uint32_t sb = smem_u32(smem);
    int* s_src = (int*)(smem + SM_IDX);
    int* s_tgt = (int*)(smem + SM_IDX + 512);

    int tid = threadIdx.x, lane = tid & 31, w = tid >> 5;
    int wm = w >> 1, wn = w & 1;
    int g = lane >> 2, tg = lane & 3;

    {
        int slot = m0 + tid;
        if (slot < cnt) {
            int e = g_bucket[t][slot];
            s_src[tid] = eidx[e];
            s_tgt[tid] = eidx[NE + e];
        } else {
            s_src[tid] = 0;
            s_tgt[tid] = -1;
        }
    }
    __syncthreads();

    const float* Wt = g_wmtf + (size_t)t * DIM * DIM;

    auto fill = [&](int stg, int kk) {
        uint32_t ab = sb + SM_TILES + stg * STG_BYTES;
        uint32_t bbs = ab + A_STG_BYTES;
#pragma unroll
        for (int p = 0; p < 8; ++p) {
            int f = p * THREADS + tid;
            int row = f >> 3, q = f & 7;
            cpa16(ab + row * (LDA * 4) + q * 16,
                  g_xtf + (size_t)s_src[row] * DIM + kk + q * 4);
        }
#pragma unroll
        for (int p = 0; p < 8; ++p) {
            int f = p * THREADS + tid;
            int row = f >> 3, q = f & 7;
            cpa16(bbs + row * (LDA * 4) + q * 16,
                  Wt + (size_t)(n0 + row) * DIM + kk + q * 4);
        }
    };

    float c[4][8][4];
#pragma unroll
    for (int i = 0; i < 4; i++)
#pragma unroll
        for (int j = 0; j < 8; j++)
#pragma unroll
            for (int r = 0; r < 4; r++) c[i][j][r] = 0.f;

    const int KT = DIM / BK;   // 24
    fill(0, 0); cpa_commit();
    fill(1, BK); cpa_commit();

    for (int kt = 0; kt < KT; ++kt) {
        cpa_wait1();
        __syncthreads();
        if (kt + 2 < KT) fill((kt + 2) % NSTG, (kt + 2) * BK);
        cpa_commit();
        const unsigned* As = (const unsigned*)(smem + SM_TILES + (kt % NSTG) * STG_BYTES);
        const unsigned* Bs = As + BM * LDA;
        compute_stage(As, Bs, c, wm, wn, g, tg);
    }

    // epilogue: + bias, atomic scatter-add to target nodes
#pragma unroll
    for (int im = 0; im < 4; ++im) {
#pragma unroll
        for (int r2 = 0; r2 < 2; ++r2) {
            int rloc = wm * 64 + im * 16 + g + r2 * 8;
            int tgt = s_tgt[rloc];
            if (tgt < 0) continue;
            float* dst = g_agg + (size_t)tgt * DIM;
#pragma unroll
            for (int in_ = 0; in_ < 8; ++in_) {
                int col = n0 + wn * 64 + in_ * 8 + tg * 2;
                atomicAdd(dst + col,     c[im][in_][r2 * 2 + 0] + bm[t * DIM + col]);
                atomicAdd(dst + col + 1, c[im][in_][r2 * 2 + 1] + bm[t * DIM + col + 1]);
            }
        }
    }
}

// ---------------------------------------------------------------------------
// K3: update GEMM  out = relu([X | agg] @ W_upd^T + b_upd)  (residual in k_ln)
//     grid (DIM/BN, ceil(NN/BM)), 128 threads, 2 CTA/SM
// ---------------------------------------------------------------------------
__global__ __launch_bounds__(THREADS, 2) void k_upd(const float* __restrict__ bu,
                                                    float* __restrict__ out) {
    int m0 = blockIdx.y * BM;
    int n0 = blockIdx.x * BN;

    extern __shared__ char smem[];
    uint32_t sb = smem_u32(smem);

    int tid = threadIdx.x, lane = tid & 31, w = tid >> 5;
    int wm = w >> 1, wn = w & 1;
    int g = lane >> 2, tg = lane & 3;

    auto fill = [&](int stg, int kk) {
        uint32_t ab = sb + SM_TILES + stg * STG_BYTES;
        uint32_t bbs = ab + A_STG_BYTES;
        const float* abase = (kk < DIM) ? g_xtf + kk : g_agg + (kk - DIM);
#pragma unroll
        for (int p = 0; p < 8; ++p) {
            int f = p * THREADS + tid;
            int row = f >> 3, q = f & 7;
            int node = m0 + row; if (node >= NN) node = NN - 1;
            cpa16(ab + row * (LDA * 4) + q * 16, abase + (size_t)node * DIM + q * 4);
        }
#pragma unroll
        for (int p = 0; p < 8; ++p) {
            int f = p * THREADS + tid;
            int row = f >> 3, q = f & 7;
            cpa16(bbs + row * (LDA * 4) + q * 16,
                  g_wutf + (size_t)(n0 + row) * DIM2 + kk + q * 4);
        }
    };

    float c[4][8][4];
#pragma unroll
    for (int i = 0; i < 4; i++)
#pragma unroll
        for (int j = 0; j < 8; j++)
#pragma unroll
            for (int r = 0; r < 4; r++) c[i][j][r] = 0.f;

    const int KT = DIM2 / BK;  // 48
    fill(0, 0); cpa_commit();
    fill(1, BK); cpa_commit();

    for (int kt = 0; kt < KT; ++kt) {
        cpa_wait1();
        __syncthreads();
        if (kt + 2 < KT) fill((kt + 2) % NSTG, (kt + 2) * BK);
        cpa_commit();
        const unsigned* As = (const unsigned*)(smem + SM_TILES + (kt % NSTG) * STG_BYTES);
        const unsigned* Bs = As + BM * LDA;
        compute_stage(As, Bs, c, wm, wn, g, tg);
    }

    // epilogue: bias + relu, float2 stores
#pragma unroll
    for (int im = 0; im < 4; ++im) {
#pragma unroll
        for (int r2 = 0; r2 < 2; ++r2) {
            int rloc = wm * 64 + im * 16 + g + r2 * 8;
            int node = m0 + rloc;
            if (node >= NN) continue;
#pragma unroll
            for (int in_ = 0; in_ < 8; ++in_) {
                int col = n0 + wn * 64 + in_ * 8 + tg * 2;
                float2 o;
                o.x = fmaxf(c[im][in_][r2 * 2 + 0] + bu[col],     0.f);
                o.y = fmaxf(c[im][in_][r2 * 2 + 1] + bu[col + 1], 0.f);
                *reinterpret_cast<float2*>(out + (size_t)node * DIM + col) = o;
            }
        }
    }
}

// ---------------------------------------------------------------------------
// K4: out = LayerNorm(X + out) — residual folded in (full-precision X)
// ---------------------------------------------------------------------------
__global__ __launch_bounds__(256) void k_ln(float* __restrict__ out,
                                            const float* __restrict__ X,
                                            const float* __restrict__ gamma,
                                            const float* __restrict__ beta) {
    __shared__ float red[34];
    int n = blockIdx.x;
    float* row = out + (size_t)n * DIM;
    const float* xr = X + (size_t)n * DIM;
    int tid = threadIdx.x;

    float v0 = row[tid]       + xr[tid];
    float v1 = row[tid + 256] + xr[tid + 256];
    float v2 = row[tid + 512] + xr[tid + 512];
    float s = v0 + v1 + v2;
    float s2 = v0 * v0 + v1 * v1 + v2 * v2;
#pragma unroll
    for (int o = 16; o > 0; o >>= 1) {
        s  += __shfl_xor_sync(0xffffffffu, s, o);
        s2 += __shfl_xor_sync(0xffffffffu, s2, o);
    }
    int w = tid >> 5, l = tid & 31;
    if (l == 0) { red[w] = s; red[8 + w] = s2; }
    __syncthreads();
    if (w == 0) {
        float a = (l < 8) ? red[l] : 0.f;
        float b = (l < 8) ? red[8 + l] : 0.f;
#pragma unroll
        for (int o = 4; o > 0; o >>= 1) {
            a += __shfl_xor_sync(0xffffffffu, a, o);
            b += __shfl_xor_sync(0xffffffffu, b, o);
        }
        if (l == 0) { red[32] = a; red[33] = b; }
    }
    __syncthreads();
    float mu = red[32] * (1.0f / DIM);
    float var = red[33] * (1.0f / DIM) - mu * mu;
    float inv = rsqrtf(var + LN_EPS);
    row[tid]       = (v0 - mu) * inv * gamma[tid]       + beta[tid];
    row[tid + 256] = (v1 - mu) * inv * gamma[tid + 256] + beta[tid + 256];
    row[tid + 512] = (v2 - mu) * inv * gamma[tid + 512] + beta[tid + 512];
}

// ---------------------------------------------------------------------------
// kernel_launch
// ---------------------------------------------------------------------------
extern "C" void kernel_launch(void* const* d_in, const int* in_sizes, int n_in,
                              void* d_out, int out_size) {
    const float* X   = (const float*)d_in[0];
    const float* Wm  = (const float*)d_in[1];
    const float* bm  = (const float*)d_in[2];
    const float* Wu  = (const float*)d_in[3];
    const float* bu  = (const float*)d_in[4];
    const float* gam = (const float*)d_in[5];
    const float* bet = (const float*)d_in[6];
    const int*   eidx= (const int*)d_in[7];
    const int*   etyp= (const int*)d_in[8];
    float* out = (float*)d_out;

    (void)in_sizes; (void)n_in; (void)out_size;

    cudaFuncSetAttribute(k_msg, cudaFuncAttributeMaxDynamicSharedMemorySize, SMEM_SZ);
    cudaFuncSetAttribute(k_upd, cudaFuncAttributeMaxDynamicSharedMemorySize, SMEM_SZ);

    float* xtf;  cudaGetSymbolAddress((void**)&xtf,  g_xtf);
    float* wmtf; cudaGetSymbolAddress((void**)&wmtf, g_wmtf);
    float* wutf; cudaGetSymbolAddress((void**)&wutf, g_wutf);
    float* agg;  cudaGetSymbolAddress((void**)&agg,  g_agg);

    k_init<<<4096, 256>>>();
    k_bucket<<<(NE + 255) / 256, 256>>>(etyp);

    // tf32-round inputs once (removes cvt from GEMM hot loops)
    k_cvt<<<4096, 256>>>(X,  xtf,  (size_t)NN * DIM / 4);
    k_cvt<<<1024, 256>>>(Wm, wmtf, (size_t)NT * DIM * DIM / 4);
    k_cvt<<<512,  256>>>(Wu, wutf, (size_t)DIM * DIM2 / 4);

    dim3 gm(DIM / BN, (NE + BM - 1) / BM, NT);
    k_msg<<<gm, THREADS, SMEM_SZ>>>(bm, eidx);

    // round aggregated messages in place before the update GEMM
    k_cvt<<<4096, 256>>>(agg, agg, (size_t)NN * DIM / 4);

    dim3 gu(DIM / BN, (NN + BM - 1) / BM);
    k_upd<<<gu, THREADS, SMEM_SZ>>>(bu, out);

    k_ln<<<NN, 256>>>(out, X, gam, bet);
}

// round 8
// speedup vs baseline: 1.8165x; 1.0122x over previous
#include <cuda_runtime.h>
#include <cstdint>
#include <cstddef>

// ---------------------------------------------------------------------------
// Problem constants
// ---------------------------------------------------------------------------
#define NN   100000
#define NE   100000
#define DIM  768
#define DIM2 1536
#define NT   5
#define LN_EPS 1e-5f

// Tiling: CTA tile 128x128, 4 warps in 2x2, warp tile 64x64, BK=32, 2 stages
// LDA=48 floats (192B row): conflict-free LDS.128 fragment loads.
// smem = 99328B -> 2 CTAs/SM.
#define BM 128
#define BN 128
#define BK 32
#define THREADS 128
#define LDA 48
#define A_STG_BYTES (BM * LDA * 4)          // 24576
#define B_STG_BYTES (BN * LDA * 4)          // 24576
#define STG_BYTES   (A_STG_BYTES + B_STG_BYTES)  // 49152
#define SM_IDX   0              // 1024 bytes: s_src(512) + s_tgt(512)
#define SM_TILES 1024
#define SMEM_SZ  (SM_TILES + 2 * STG_BYTES)      // 99328

// ---------------------------------------------------------------------------
// Device scratch. All tf32 copies are stored K-PERMUTED: within each group of
// 16 K-elements, phys[4t+j] = logical[t+4j]  (t,j in 0..3). Each thread's MMA
// fragment elements for two k-steps are then contiguous (one LDS.128).
// A and B share the permutation, so products pair identically -> numerics
// are bit-identical to the unpermuted kernel.
// ---------------------------------------------------------------------------
__device__ float g_agg[(size_t)NN * DIM];          // logical until k_cvtp pass
__device__ float g_xtf[(size_t)NN * DIM];          // tf32 + permuted
__device__ float g_wmtf[(size_t)NT * DIM * DIM];   // tf32 + permuted
__device__ float g_wutf[(size_t)DIM * DIM2];       // tf32 + permuted
__device__ int   g_bucket[NT][NE];
__device__ int   g_count[NT];

// ---------------------------------------------------------------------------
// Helpers
// ---------------------------------------------------------------------------
__device__ __forceinline__ uint32_t smem_u32(const void* p) {
    uint32_t a;
    asm("{ .reg .u64 t; cvta.to.shared.u64 t, %1; cvt.u32.u64 %0, t; }"
        : "=r"(a) : "l"(p));
    return a;
}

__device__ __forceinline__ void cpa16(uint32_t s, const void* g) {
    asm volatile("cp.async.cg.shared.global [%0], [%1], 16;"
                 :: "r"(s), "l"(g) : "memory");
}
__device__ __forceinline__ void cpa_commit() {
    asm volatile("cp.async.commit_group;" ::: "memory");
}
__device__ __forceinline__ void cpa_wait1() {
    asm volatile("cp.async.wait_group 1;" ::: "memory");
}
__device__ __forceinline__ void cpa_wait0() {
    asm volatile("cp.async.wait_group 0;" ::: "memory");
}

__device__ __forceinline__ float f2tf_f(float x) {
    unsigned r;
    asm("cvt.rna.tf32.f32 %0, %1;" : "=r"(r) : "f"(x));
    return __uint_as_float(r);
}

__device__ __forceinline__ void mma8(float& c0, float& c1, float& c2, float& c3,
                                     unsigned a0, unsigned a1, unsigned a2, unsigned a3,
                                     unsigned b0, unsigned b1) {
    asm volatile(
        "mma.sync.aligned.m16n8k8.row.col.f32.tf32.tf32.f32 "
        "{%0,%1,%2,%3}, {%4,%5,%6,%7}, {%8,%9}, {%0,%1,%2,%3};\n"
        : "+f"(c0), "+f"(c1), "+f"(c2), "+f"(c3)
        : "r"(a0), "r"(a1), "r"(a2), "r"(a3), "r"(b0), "r"(b1));
}

// one BK=32 slice: 2 k-pairs, each pair = LDS.128 frags + 2 k-steps of MMA
__device__ __forceinline__ void compute_stage(const unsigned* __restrict__ As,
                                              const unsigned* __restrict__ Bs,
                                              float c[4][8][4],
                                              int wm, int wn, int g, int tg) {
#pragma unroll
    for (int kp = 0; kp < 2; ++kp) {
        uint4 a[4][2], b[8];
#pragma unroll
        for (int im = 0; im < 4; ++im) {
            int mb = wm * 64 + im * 16;
            a[im][0] = *reinterpret_cast<const uint4*>(&As[(mb + g) * LDA + kp * 16 + tg * 4]);
            a[im][1] = *reinterpret_cast<const uint4*>(&As[(mb + g + 8) * LDA + kp * 16 + tg * 4]);
        }
#pragma unroll
        for (int in_ = 0; in_ < 8; ++in_) {
            int nb = wn * 64 + in_ * 8 + g;
            b[in_] = *reinterpret_cast<const uint4*>(&Bs[nb * LDA + kp * 16 + tg * 4]);
        }
#pragma unroll
        for (int im = 0; im < 4; ++im)
#pragma unroll
            for (int in_ = 0; in_ < 8; ++in_) {
                mma8(c[im][in_][0], c[im][in_][1], c[im][in_][2], c[im][in_][3],
                     a[im][0].x, a[im][1].x, a[im][0].y, a[im][1].y,
                     b[in_].x, b[in_].y);
                mma8(c[im][in_][0], c[im][in_][1], c[im][in_][2], c[im][in_][3],
                     a[im][0].z, a[im][1].z, a[im][0].w, a[im][1].w,
                     b[in_].z, b[in_].w);
            }
    }
}

// ---------------------------------------------------------------------------
// K0 / K1: init + bucket
// ---------------------------------------------------------------------------
__global__ void k_init() {
    size_t idx = (size_t)blockIdx.x * blockDim.x + threadIdx.x;
    if (idx < NT) g_count[idx] = 0;
    float4* p = reinterpret_cast<float4*>(g_agg);
    size_t n4 = (size_t)NN * DIM / 4;
    size_t stride = (size_t)gridDim.x * blockDim.x;
    for (size_t i = idx; i < n4; i += stride) p[i] = make_float4(0.f, 0.f, 0.f, 0.f);
}

__global__ void k_bucket(const int* __restrict__ etype) {
    int e = blockIdx.x * blockDim.x + threadIdx.x;
    if (e < NE) {
        int t = etype[e];
        int pos = atomicAdd(&g_count[t], 1);
        g_bucket[t][pos] = e;
    }
}

// tf32-round + K-permute (4x4 transpose within each 16-float group).
// NOTE: no __restrict__ — called in-place on g_agg (group-local permutation,
// all loads precede all stores within a group).
__global__ void k_cvtp(const float* src, float* dst, size_t ngroups) {
    size_t idx = (size_t)blockIdx.x * blockDim.x + threadIdx.x;
    size_t stride = (size_t)gridDim.x * blockDim.x;
    for (size_t i = idx; i < ngroups; i += stride) {
        const float4* s = reinterpret_cast<const float4*>(src) + i * 4;
        float4 v0 = s[0], v1 = s[1], v2 = s[2], v3 = s[3];
        float4* d = reinterpret_cast<float4*>(dst) + i * 4;
        float4 o;
        o.x = f2tf_f(v0.x); o.y = f2tf_f(v1.x); o.z = f2tf_f(v2.x); o.w = f2tf_f(v3.x);
        d[0] = o;
        o.x = f2tf_f(v0.y); o.y = f2tf_f(v1.y); o.z = f2tf_f(v2.y); o.w = f2tf_f(v3.y);
        d[1] = o;
        o.x = f2tf_f(v0.z); o.y = f2tf_f(v1.z); o.z = f2tf_f(v2.z); o.w = f2tf_f(v3.z);
        d[2] = o;
        o.x = f2tf_f(v0.w); o.y = f2tf_f(v1.w); o.z = f2tf_f(v2.w); o.w = f2tf_f(v3.w);
        d[3] = o;
    }
}

// ---------------------------------------------------------------------------
// K2: per-type gather-GEMM, atomic scatter-add into g_agg
//     grid (DIM/BN, ceil(NE/BM), NT), 128 threads, 2 CTA/SM
// ---------------------------------------------------------------------------
__global__ __launch_bounds__(THREADS, 2) void k_msg(const float* __restrict__ bm,
                                                    const int*   __restrict__ eidx) {
    int t = blockIdx.z;
    int cnt = g_count[t];
    int m0 = blockIdx.y * BM;
    if (m0 >= cnt) return;
    int n0 = blockIdx.x * BN;

    extern __shared__ char smem[];
    uint32_t sb = smem_u32(smem);
    int* s_src = (int*)(smem + SM_IDX);
    int* s_tgt = (int*)(smem + SM_IDX + 512);

    int tid = threadIdx.x, lane = tid & 31, w = tid >> 5;
    int wm = w >> 1, wn = w & 1;
    int g = lane >> 2, tg = lane & 3;

    {
        int slot = m0 + tid;
        if (slot < cnt) {
            int e = g_bucket[t][slot];
            s_src[tid] = eidx[e];
            s_tgt[tid] = eidx[NE + e];
        } else {
            s_src[tid] = 0;
            s_tgt[tid] = -1;
        }
    }
    __syncthreads();

    const float* Wt = g_wmtf + (size_t)t * DIM * DIM;

    auto fill = [&](int stg, int kk) {
        uint32_t ab = sb + SM_TILES + stg * STG_BYTES;
        uint32_t bbs = ab + A_STG_BYTES;
#pragma unroll
        for (int p = 0; p < 8; ++p) {
            int f = p * THREADS + tid;
            int row = f >> 3, q = f & 7;
            cpa16(ab + row * (LDA * 4) + q * 16,
                  g_xtf + (size_t)s_src[row] * DIM + kk + q * 4);
        }
#pragma unroll
        for (int p = 0; p < 8; ++p) {
            int f = p * THREADS + tid;
            int row = f >> 3, q = f & 7;
            cpa16(bbs + row * (LDA * 4) + q * 16,
                  Wt + (size_t)(n0 + row) * DIM + kk + q * 4);
        }
    };

    float c[4][8][4];
#pragma unroll
    for (int i = 0; i < 4; i++)
#pragma unroll
        for (int j = 0; j < 8; j++)
#pragma unroll
            for (int r = 0; r < 4; r++) c[i][j][r] = 0.f;

    const int KT = DIM / BK;   // 24
    fill(0, 0); cpa_commit();
    fill(1, BK); cpa_commit();

    for (int kt = 0; kt < KT; ++kt) {
        if (kt == KT - 1) cpa_wait0(); else cpa_wait1();
        __syncthreads();
        const unsigned* As = (const unsigned*)(smem + SM_TILES + (kt & 1) * STG_BYTES);
        const unsigned* Bs = As + BM * LDA;
        compute_stage(As, Bs, c, wm, wn, g, tg);
        __syncthreads();
        if (kt + 2 < KT) fill(kt & 1, (kt + 2) * BK);
        cpa_commit();   // unconditional: keeps wait_group accounting correct
    }

    // epilogue: + bias, atomic scatter-add to target nodes
#pragma unroll
    for (int im = 0; im < 4; ++im) {
#pragma unroll
        for (int r2 = 0; r2 < 2; ++r2) {
            int rloc = wm * 64 + im * 16 + g + r2 * 8;
            int tgt = s_tgt[rloc];
            if (tgt < 0) continue;
            float* dst = g_agg + (size_t)tgt * DIM;
#pragma unroll
            for (int in_ = 0; in_ < 8; ++in_) {
                int col = n0 + wn * 64 + in_ * 8 + tg * 2;
                atomicAdd(dst + col,     c[im][in_][r2 * 2 + 0] + bm[t * DIM + col]);
                atomicAdd(dst + col + 1, c[im][in_][r2 * 2 + 1] + bm[t * DIM + col + 1]);
            }
        }
    }
}

// ---------------------------------------------------------------------------
// K3: update GEMM  out = relu([X | agg] @ W_upd^T + b_upd)  (residual in k_ln)
//     grid (DIM/BN, ceil(NN/BM)), 128 threads, 2 CTA/SM
// ---------------------------------------------------------------------------
__global__ __launch_bounds__(THREADS, 2) void k_upd(const float* __restrict__ bu,
                                                    float* __restrict__ out) {
    int m0 = blockIdx.y * BM;
    int n0 = blockIdx.x * BN;

    extern __shared__ char smem[];
    uint32_t sb = smem_u32(smem);

    int tid = threadIdx.x, lane = tid & 31, w = tid >> 5;
    int wm = w >> 1, wn = w & 1;
    int g = lane >> 2, tg = lane & 3;

    auto fill = [&](int stg, int kk) {
        uint32_t ab = sb + SM_TILES + stg * STG_BYTES;
        uint32_t bbs = ab + A_STG_BYTES;
        const float* abase = (kk < DIM) ? g_xtf + kk : g_agg + (kk - DIM);
#pragma unroll
        for (int p = 0; p < 8; ++p) {
            int f = p * THREADS + tid;
            int row = f >> 3, q = f & 7;
            int node = m0 + row; if (node >= NN) node = NN - 1;
            cpa16(ab + row * (LDA * 4) + q * 16, abase + (size_t)node * DIM + q * 4);
        }
#pragma unroll
        for (int p = 0; p < 8; ++p) {
            int f = p * THREADS + tid;
            int row = f >> 3, q = f & 7;
            cpa16(bbs + row * (LDA * 4) + q * 16,
                  g_wutf + (size_t)(n0 + row) * DIM2 + kk + q * 4);
        }
    };

    float c[4][8][4];
#pragma unroll
    for (int i = 0; i < 4; i++)
#pragma unroll
        for (int j = 0; j < 8; j++)
#pragma unroll
            for (int r = 0; r < 4; r++) c[i][j][r] = 0.f;

    const int KT = DIM2 / BK;  // 48
    fill(0, 0); cpa_commit();
    fill(1, BK); cpa_commit();

    for (int kt = 0; kt < KT; ++kt) {
        if (kt == KT - 1) cpa_wait0(); else cpa_wait1();
        __syncthreads();
        const unsigned* As = (const unsigned*)(smem + SM_TILES + (kt & 1) * STG_BYTES);
        const unsigned* Bs = As + BM * LDA;
        compute_stage(As, Bs, c, wm, wn, g, tg);
        __syncthreads();
        if (kt + 2 < KT) fill(kt & 1, (kt + 2) * BK);
        cpa_commit();   // unconditional
    }

    // epilogue: bias + relu, float2 stores
#pragma unroll
    for (int im = 0; im < 4; ++im) {
#pragma unroll
        for (int r2 = 0; r2 < 2; ++r2) {
            int rloc = wm * 64 + im * 16 + g + r2 * 8;
            int node = m0 + rloc;
            if (node >= NN) continue;
#pragma unroll
            for (int in_ = 0; in_ < 8; ++in_) {
                int col = n0 + wn * 64 + in_ * 8 + tg * 2;
                float2 o;
                o.x = fmaxf(c[im][in_][r2 * 2 + 0] + bu[col],     0.f);
                o.y = fmaxf(c[im][in_][r2 * 2 + 1] + bu[col + 1], 0.f);
                *reinterpret_cast<float2*>(out + (size_t)node * DIM + col) = o;
            }
        }
    }
}

// ---------------------------------------------------------------------------
// K4: out = LayerNorm(X + out) — residual folded in (full-precision X)
// ---------------------------------------------------------------------------
__global__ __launch_bounds__(256) void k_ln(float* __restrict__ out,
                                            const float* __restrict__ X,
                                            const float* __restrict__ gamma,
                                            const float* __restrict__ beta) {
    __shared__ float red[34];
    int n = blockIdx.x;
    float* row = out + (size_t)n * DIM;
    const float* xr = X + (size_t)n * DIM;
    int tid = threadIdx.x;

    float v0 = row[tid]       + xr[tid];
    float v1 = row[tid + 256] + xr[tid + 256];
    float v2 = row[tid + 512] + xr[tid + 512];
    float s = v0 + v1 + v2;
    float s2 = v0 * v0 + v1 * v1 + v2 * v2;
#pragma unroll
    for (int o = 16; o > 0; o >>= 1) {
        s  += __shfl_xor_sync(0xffffffffu, s, o);
        s2 += __shfl_xor_sync(0xffffffffu, s2, o);
    }
    int w = tid >> 5, l = tid & 31;
    if (l == 0) { red[w] = s; red[8 + w] = s2; }
    __syncthreads();
    if (w == 0) {
        float a = (l < 8) ? red[l] : 0.f;
        float b = (l < 8) ? red[8 + l] : 0.f;
#pragma unroll
        for (int o = 4; o > 0; o >>= 1) {
            a += __shfl_xor_sync(0xffffffffu, a, o);
            b += __shfl_xor_sync(0xffffffffu, b, o);
        }
        if (l == 0) { red[32] = a; red[33] = b; }
    }
    __syncthreads();
    float mu = red[32] * (1.0f / DIM);
    float var = red[33] * (1.0f / DIM) - mu * mu;
    float inv = rsqrtf(var + LN_EPS);
    row[tid]       = (v0 - mu) * inv * gamma[tid]       + beta[tid];
    row[tid + 256] = (v1 - mu) * inv * gamma[tid + 256] + beta[tid + 256];
    row[tid + 512] = (v2 - mu) * inv * gamma[tid + 512] + beta[tid + 512];
}

// ---------------------------------------------------------------------------
// kernel_launch
// ---------------------------------------------------------------------------
extern "C" void kernel_launch(void* const* d_in, const int* in_sizes, int n_in,
                              void* d_out, int out_size) {
    const float* X   = (const float*)d_in[0];
    const float* Wm  = (const float*)d_in[1];
    const float* bm  = (const float*)d_in[2];
    const float* Wu  = (const float*)d_in[3];
    const float* bu  = (const float*)d_in[4];
    const float* gam = (const float*)d_in[5];
    const float* bet = (const float*)d_in[6];
    const int*   eidx= (const int*)d_in[7];
    const int*   etyp= (const int*)d_in[8];
    float* out = (float*)d_out;

    (void)in_sizes; (void)n_in; (void)out_size;

    cudaFuncSetAttribute(k_msg, cudaFuncAttributeMaxDynamicSharedMemorySize, SMEM_SZ);
    cudaFuncSetAttribute(k_upd, cudaFuncAttributeMaxDynamicSharedMemorySize, SMEM_SZ);

    float* xtf;  cudaGetSymbolAddress((void**)&xtf,  g_xtf);
    float* wmtf; cudaGetSymbolAddress((void**)&wmtf, g_wmtf);
    float* wutf; cudaGetSymbolAddress((void**)&wutf, g_wutf);
    float* agg;  cudaGetSymbolAddress((void**)&agg,  g_agg);

    k_init<<<4096, 256>>>();
    k_bucket<<<(NE + 255) / 256, 256>>>(etyp);

    // tf32-round + K-permute inputs once
    k_cvtp<<<4096, 256>>>(X,  xtf,  (size_t)NN * DIM / 16);
    k_cvtp<<<1024, 256>>>(Wm, wmtf, (size_t)NT * DIM * DIM / 16);
    k_cvtp<<<512,  256>>>(Wu, wutf, (size_t)DIM * DIM2 / 16);

    dim3 gm(DIM / BN, (NE + BM - 1) / BM, NT);
    k_msg<<<gm, THREADS, SMEM_SZ>>>(bm, eidx);

    // round + permute aggregated messages in place before the update GEMM
    k_cvtp<<<4096, 256>>>(agg, agg, (size_t)NN * DIM / 16);

    dim3 gu(DIM / BN, (NN + BM - 1) / BM);
    k_upd<<<gu, THREADS, SMEM_SZ>>>(bu, out);

    k_ln<<<NN, 256>>>(out, X, gam, bet);
}

// round 10
// speedup vs baseline: 1.8837x; 1.0370x over previous
#include <cuda_runtime.h>
#include <cstdint>
#include <cstddef>

// ---------------------------------------------------------------------------
// Problem constants
// ---------------------------------------------------------------------------
#define NN   100000
#define NE   100000
#define DIM  768
#define DIM2 1536
#define NT   5
#define LN_EPS 1e-5f

// Tiling: CTA 128x128, 4 warps in 2x2, warp tile 64x64, BK=32, 3 stages.
// LDA=32 (no pad) + XOR swizzle on 16B chunks: conflict-free LDS.128 AND
// compact smem (32KB/stage) -> 3 stages, 1 barrier/slice, 2 CTAs/SM.
#define BM 128
#define BN 128
#define BK 32
#define THREADS 128
#define LDA 32
#define A_STG_BYTES (BM * LDA * 4)          // 16384
#define B_STG_BYTES (BN * LDA * 4)          // 16384
#define STG_BYTES   (A_STG_BYTES + B_STG_BYTES)  // 32768
#define SM_IDX   0              // 1024 bytes: s_src(512) + s_tgt(512)
#define SM_TILES 1024
#define SMEM_SZ  (SM_TILES + 3 * STG_BYTES)      // 99328

// ---------------------------------------------------------------------------
// Device scratch. tf32 copies stored K-PERMUTED: in each 16-float K-group,
// phys[4t+j] = logical[t+4j]; fragment elements for two k-steps contiguous.
// ---------------------------------------------------------------------------
__device__ float g_agg[(size_t)NN * DIM];
__device__ float g_xtf[(size_t)NN * DIM];
__device__ float g_wmtf[(size_t)NT * DIM * DIM];
__device__ float g_wutf[(size_t)DIM * DIM2];
__device__ int   g_bucket[NT][NE];
__device__ int   g_count[NT];

// ---------------------------------------------------------------------------
// Helpers
// ---------------------------------------------------------------------------
__device__ __forceinline__ uint32_t smem_u32(const void* p) {
    uint32_t a;
    asm("{ .reg .u64 t; cvta.to.shared.u64 t, %1; cvt.u32.u64 %0, t; }"
        : "=r"(a) : "l"(p));
    return a;
}

__device__ __forceinline__ void cpa16(uint32_t s, const void* g) {
    asm volatile("cp.async.cg.shared.global [%0], [%1], 16;"
                 :: "r"(s), "l"(g) : "memory");
}
__device__ __forceinline__ void cpa_commit() {
    asm volatile("cp.async.commit_group;" ::: "memory");
}
__device__ __forceinline__ void cpa_wait1() {
    asm volatile("cp.async.wait_group 1;" ::: "memory");
}
__device__ __forceinline__ void cpa_wait0() {
    asm volatile("cp.async.wait_group 0;" ::: "memory");
}

__device__ __forceinline__ float f2tf_f(float x) {
    unsigned r;
    asm("cvt.rna.tf32.f32 %0, %1;" : "=r"(r) : "f"(x));
    return __uint_as_float(r);
}

__device__ __forceinline__ void mma8(float& c0, float& c1, float& c2, float& c3,
                                     unsigned a0, unsigned a1, unsigned a2, unsigned a3,
                                     unsigned b0, unsigned b1) {
    asm volatile(
        "mma.sync.aligned.m16n8k8.row.col.f32.tf32.tf32.f32 "
        "{%0,%1,%2,%3}, {%4,%5,%6,%7}, {%8,%9}, {%0,%1,%2,%3};\n"
        : "+f"(c0), "+f"(c1), "+f"(c2), "+f"(c3)
        : "r"(a0), "r"(a1), "r"(a2), "r"(a3), "r"(b0), "r"(b1));
}

// one BK=32 slice: 2 k-pairs; swizzled LDS.128 fragment loads + 2 k-steps MMA.
// Swizzle: chunk' = chunk ^ ((row&1)<<2); all rows a thread touches share
// parity (g&1), so the XOR value is per-thread constant.
__device__ __forceinline__ void compute_stage(const unsigned* __restrict__ As,
                                              const unsigned* __restrict__ Bs,
                                              float c[4][8][4],
                                              int wm, int wn, int g, int tg) {
    int xorv = (g & 1) << 2;
#pragma unroll
    for (int kp = 0; kp < 2; ++kp) {
        int cf = ((kp * 4 + tg) ^ xorv) * 4;   // float offset within 32-float row
        uint4 a[4][2], b[8];
#pragma unroll
        for (int im = 0; im < 4; ++im) {
            int mb = wm * 64 + im * 16;
            a[im][0] = *reinterpret_cast<const uint4*>(&As[(mb + g) * LDA + cf]);
            a[im][1] = *reinterpret_cast<const uint4*>(&As[(mb + g + 8) * LDA + cf]);
        }
#pragma unroll
        for (int in_ = 0; in_ < 8; ++in_) {
            int nb = wn * 64 + in_ * 8 + g;
            b[in_] = *reinterpret_cast<const uint4*>(&Bs[nb * LDA + cf]);
        }
#pragma unroll
        for (int im = 0; im < 4; ++im)
#pragma unroll
            for (int in_ = 0; in_ < 8; ++in_) {
                mma8(c[im][in_][0], c[im][in_][1], c[im][in_][2], c[im][in_][3],
                     a[im][0].x, a[im][1].x, a[im][0].y, a[im][1].y,
                     b[in_].x, b[in_].y);
                mma8(c[im][in_][0], c[im][in_][1], c[im][in_][2], c[im][in_][3],
                     a[im][0].z, a[im][1].z, a[im][0].w, a[im][1].w,
                     b[in_].z, b[in_].w);
            }
    }
}

// ---------------------------------------------------------------------------
// K0 / K1: init + bucket
// ---------------------------------------------------------------------------
__global__ void k_init() {
    size_t idx = (size_t)blockIdx.x * blockDim.x + threadIdx.x;
    if (idx < NT) g_count[idx] = 0;
    float4* p = reinterpret_cast<float4*>(g_agg);
    size_t n4 = (size_t)NN * DIM / 4;
    size_t stride = (size_t)gridDim.x * blockDim.x;
    for (size_t i = idx; i < n4; i += stride) p[i] = make_float4(0.f, 0.f, 0.f, 0.f);
}

__global__ void k_bucket(const int* __restrict__ etype) {
    int e = blockIdx.x * blockDim.x + threadIdx.x;
    if (e < NE) {
        int t = etype[e];
        int pos = atomicAdd(&g_count[t], 1);
        g_bucket[t][pos] = e;
    }
}

// tf32-round + K-permute one 16-float group
__device__ __forceinline__ void cvtp_group(const float* src, float* dst, size_t i) {
    const float4* s = reinterpret_cast<const float4*>(src) + i * 4;
    float4 v0 = s[0], v1 = s[1], v2 = s[2], v3 = s[3];
    float4* d = reinterpret_cast<float4*>(dst) + i * 4;
    float4 o;
    o.x = f2tf_f(v0.x); o.y = f2tf_f(v1.x); o.z = f2tf_f(v2.x); o.w = f2tf_f(v3.x);
    d[0] = o;
    o.x = f2tf_f(v0.y); o.y = f2tf_f(v1.y); o.z = f2tf_f(v2.y); o.w = f2tf_f(v3.y);
    d[1] = o;
    o.x = f2tf_f(v0.z); o.y = f2tf_f(v1.z); o.z = f2tf_f(v2.z); o.w = f2tf_f(v3.z);
    d[2] = o;
    o.x = f2tf_f(v0.w); o.y = f2tf_f(v1.w); o.z = f2tf_f(v2.w); o.w = f2tf_f(v3.w);
    d[3] = o;
}

__global__ void k_cvtp(const float* src, float* dst, size_t ngroups) {
    size_t idx = (size_t)blockIdx.x * blockDim.x + threadIdx.x;
    size_t stride = (size_t)gridDim.x * blockDim.x;
    for (size_t i = idx; i < ngroups; i += stride) cvtp_group(src, dst, i);
}

__global__ void k_cvtp3(const float* s0, float* d0, size_t n0,
                        const float* s1, float* d1, size_t n1,
                        const float* s2, float* d2, size_t n2) {
    size_t idx = (size_t)blockIdx.x * blockDim.x + threadIdx.x;
    size_t stride = (size_t)gridDim.x * blockDim.x;
    size_t total = n0 + n1 + n2;
    for (size_t i = idx; i < total; i += stride) {
        if (i < n0) cvtp_group(s0, d0, i);
        else if (i < n0 + n1) cvtp_group(s1, d1, i - n0);
        else cvtp_group(s2, d2, i - n0 - n1);
    }
}

// ---------------------------------------------------------------------------
// K2: per-type gather-GEMM, atomic scatter-add into g_agg
//     grid (DIM/BN, ceil(NE/BM), NT), 128 threads, 2 CTA/SM
// ---------------------------------------------------------------------------
__global__ __launch_bounds__(THREADS, 2) void k_msg(const float* __restrict__ bm,
                                                    const int*   __restrict__ eidx) {
    int t = blockIdx.z;
    int cnt = g_count[t];
    int m0 = blockIdx.y * BM;
    if (m0 >= cnt) return;
    int n0 = blockIdx.x * BN;

    extern __shared__ char smem[];
    uint32_t sb = smem_u32(smem);
    int* s_src = (int*)(smem + SM_IDX);
    int* s_tgt = (int*)(smem + SM_IDX + 512);

    int tid = threadIdx.x, lane = tid & 31, w = tid >> 5;
    int wm = w >> 1, wn = w & 1;
    int g = lane >> 2, tg = lane & 3;

    {
        int slot = m0 + tid;
        if (slot < cnt) {
            int e = g_bucket[t][slot];
            s_src[tid] = eidx[e];
            s_tgt[tid] = eidx[NE + e];
        } else {
            s_src[tid] = 0;
            s_tgt[tid] = -1;
        }
    }
    __syncthreads();

    const float* Wt = g_wmtf + (size_t)t * DIM * DIM;

    // fill: 128 rows x 8 chunks = 1024 chunks per tile -> p<8 with 128 threads
    auto fill = [&](int stg, int kk) {
        uint32_t ab = sb + SM_TILES + stg * STG_BYTES;
        uint32_t bbs = ab + A_STG_BYTES;
#pragma unroll
        for (int p = 0; p < 8; ++p) {
            int f = p * THREADS + tid;
            int row = f >> 3, q = f & 7;
            int qs = q ^ ((row & 1) << 2);
            cpa16(ab + row * (LDA * 4) + qs * 16,
                  g_xtf + (size_t)s_src[row] * DIM + kk + q * 4);
        }
#pragma unroll
        for (int p = 0; p < 8; ++p) {
            int f = p * THREADS + tid;
            int row = f >> 3, q = f & 7;
            int qs = q ^ ((row & 1) << 2);
            cpa16(bbs + row * (LDA * 4) + qs * 16,
                  Wt + (size_t)(n0 + row) * DIM + kk + q * 4);
        }
    };

    float c[4][8][4];
#pragma unroll
    for (int i = 0; i < 4; i++)
#pragma unroll
        for (int j = 0; j < 8; j++)
#pragma unroll
            for (int r = 0; r < 4; r++) c[i][j][r] = 0.f;

    const int KT = DIM / BK;   // 24
    fill(0, 0); cpa_commit();
    fill(1, BK); cpa_commit();

    for (int kt = 0; kt < KT; ++kt) {
        if (kt == KT - 1) cpa_wait0(); else cpa_wait1();
        __syncthreads();   // single barrier per slice (3-stage rotation is safe)
        const unsigned* As = (const unsigned*)(smem + SM_TILES + (kt % 3) * STG_BYTES);
        const unsigned* Bs = As + BM * LDA;
        compute_stage(As, Bs, c, wm, wn, g, tg);
        if (kt + 2 < KT) fill((kt + 2) % 3, (kt + 2) * BK);
        cpa_commit();      // unconditional: keeps wait_group accounting exact
    }

    // epilogue: + bias, atomic scatter-add to target nodes
#pragma unroll
    for (int im = 0; im < 4; ++im) {
#pragma unroll
        for (int r2 = 0; r2 < 2; ++r2) {
            int rloc = wm * 64 + im * 16 + g + r2 * 8;
            int tgt = s_tgt[rloc];
            if (tgt < 0) continue;
            float* dst = g_agg + (size_t)tgt * DIM;
#pragma unroll
            for (int in_ = 0; in_ < 8; ++in_) {
                int col = n0 + wn * 64 + in_ * 8 + tg * 2;
                atomicAdd(dst + col,     c[im][in_][r2 * 2 + 0] + bm[t * DIM + col]);
                atomicAdd(dst + col + 1, c[im][in_][r2 * 2 + 1] + bm[t * DIM + col + 1]);
            }
        }
    }
}

// ---------------------------------------------------------------------------
// K3: update GEMM  out = relu([X | agg] @ W_upd^T + b_upd)  (residual in k_ln)
//     grid (DIM/BN, ceil(NN/BM)), 128 threads, 2 CTA/SM
// ---------------------------------------------------------------------------
__global__ __launch_bounds__(THREADS, 2) void k_upd(const float* __restrict__ bu,
                                                    float* __restrict__ out) {
    int m0 = blockIdx.y * BM;
    int n0 = blockIdx.x * BN;

    extern __shared__ char smem[];
    uint32_t sb = smem_u32(smem);

    int tid = threadIdx.x, lane = tid & 31, w = tid >> 5;
    int wm = w >> 1, wn = w & 1;
    int g = lane >> 2, tg = lane & 3;

    auto fill = [&](int stg, int kk) {
        uint32_t ab = sb + SM_TILES + stg * STG_BYTES;
        uint32_t bbs = ab + A_STG_BYTES;
        const float* abase = (kk < DIM) ? g_xtf + kk : g_agg + (kk - DIM);
#pragma unroll
        for (int p = 0; p < 8; ++p) {
            int f = p * THREADS + tid;
            int row = f >> 3, q = f & 7;
            int qs = q ^ ((row & 1) << 2);
            int node = m0 + row; if (node >= NN) node = NN - 1;
            cpa16(ab + row * (LDA * 4) + qs * 16, abase + (size_t)node * DIM + q * 4);
        }
#pragma unroll
        for (int p = 0; p < 8; ++p) {
            int f = p * THREADS + tid;
            int row = f >> 3, q = f & 7;
            int qs = q ^ ((row & 1) << 2);
            cpa16(bbs + row * (LDA * 4) + qs * 16,
                  g_wutf + (size_t)(n0 + row) * DIM2 + kk + q * 4);
        }
    };

    float c[4][8][4];
#pragma unroll
    for (int i = 0; i < 4; i++)
#pragma unroll
        for (int j = 0; j < 8; j++)
#pragma unroll
            for (int r = 0; r < 4; r++) c[i][j][r] = 0.f;

    const int KT = DIM2 / BK;  // 48
    fill(0, 0); cpa_commit();
    fill(1, BK); cpa_commit();

    for (int kt = 0; kt < KT; ++kt) {
        if (kt == KT - 1) cpa_wait0(); else cpa_wait1();
        __syncthreads();
        const unsigned* As = (const unsigned*)(smem + SM_TILES + (kt % 3) * STG_BYTES);
        const unsigned* Bs = As + BM * LDA;
        compute_stage(As, Bs, c, wm, wn, g, tg);
        if (kt + 2 < KT) fill((kt + 2) % 3, (kt + 2) * BK);
        cpa_commit();
    }

    // epilogue: bias + relu, float2 stores
#pragma unroll
    for (int im = 0; im < 4; ++im) {
#pragma unroll
        for (int r2 = 0; r2 < 2; ++r2) {
            int rloc = wm * 64 + im * 16 + g + r2 * 8;
            int node = m0 + rloc;
            if (node >= NN) continue;
#pragma unroll
            for (int in_ = 0; in_ < 8; ++in_) {
                int col = n0 + wn * 64 + in_ * 8 + tg * 2;
                float2 o;
                o.x = fmaxf(c[im][in_][r2 * 2 + 0] + bu[col],     0.f);
                o.y = fmaxf(c[im][in_][r2 * 2 + 1] + bu[col + 1], 0.f);
                *reinterpret_cast<float2*>(out + (size_t)node * DIM + col) = o;
            }
        }
    }
}

// ---------------------------------------------------------------------------
// K4: out = LayerNorm(X + out)
// ---------------------------------------------------------------------------
__global__ __launch_bounds__(256) void k_ln(float* __restrict__ out,
                                            const float* __restrict__ X,
                                            const float* __restrict__ gamma,
                                            const float* __restrict__ beta) {
    __shared__ float red[34];
    int n = blockIdx.x;
    float* row = out + (size_t)n * DIM;
    const float* xr = X + (size_t)n * DIM;
    int tid = threadIdx.x;

    float v0 = row[tid]       + xr[tid];
    float v1 = row[tid + 256] + xr[tid + 256];
    float v2 = row[tid + 512] + xr[tid + 512];
    float s = v0 + v1 + v2;
    float s2 = v0 * v0 + v1 * v1 + v2 * v2;
#pragma unroll
    for (int o = 16; o > 0; o >>= 1) {
        s  += __shfl_xor_sync(0xffffffffu, s, o);
        s2 += __shfl_xor_sync(0xffffffffu, s2, o);
    }
    int w = tid >> 5, l = tid & 31;
    if (l == 0) { red[w] = s; red[8 + w] = s2; }
    __syncthreads();
    if (w == 0) {
        float a = (l < 8) ? red[l] : 0.f;
        float b = (l < 8) ? red[8 + l] : 0.f;
#pragma unroll
        for (int o = 4; o > 0; o >>= 1) {
            a += __shfl_xor_sync(0xffffffffu, a, o);
            b += __shfl_xor_sync(0xffffffffu, b, o);
        }
        if (l == 0) { red[32] = a; red[33] = b; }
    }
    __syncthreads();
    float mu = red[32] * (1.0f / DIM);
    float var = red[33] * (1.0f / DIM) - mu * mu;
    float inv = rsqrtf(var + LN_EPS);
    row[tid]       = (v0 - mu) * inv * gamma[tid]       + beta[tid];
    row[tid + 256] = (v1 - mu) * inv * gamma[tid + 256] + beta[tid + 256];
    row[tid + 512] = (v2 - mu) * inv * gamma[tid + 512] + beta[tid + 512];
}

// ---------------------------------------------------------------------------
// kernel_launch
// ---------------------------------------------------------------------------
extern "C" void kernel_launch(void* const* d_in, const int* in_sizes, int n_in,
                              void* d_out, int out_size) {
    const float* X   = (const float*)d_in[0];
    const float* Wm  = (const float*)d_in[1];
    const float* bm  = (const float*)d_in[2];
    const float* Wu  = (const float*)d_in[3];
    const float* bu  = (const float*)d_in[4];
    const float* gam = (const float*)d_in[5];
    const float* bet = (const float*)d_in[6];
    const int*   eidx= (const int*)d_in[7];
    const int*   etyp= (const int*)d_in[8];
    float* out = (float*)d_out;

    (void)in_sizes; (void)n_in; (void)out_size;

    cudaFuncSetAttribute(k_msg, cudaFuncAttributeMaxDynamicSharedMemorySize, SMEM_SZ);
    cudaFuncSetAttribute(k_upd, cudaFuncAttributeMaxDynamicSharedMemorySize, SMEM_SZ);

    float* xtf;  cudaGetSymbolAddress((void**)&xtf,  g_xtf);
    float* wmtf; cudaGetSymbolAddress((void**)&wmtf, g_wmtf);
    float* wutf; cudaGetSymbolAddress((void**)&wutf, g_wutf);
    float* agg;  cudaGetSymbolAddress((void**)&agg,  g_agg);

    k_init<<<4096, 256>>>();
    k_bucket<<<(NE + 255) / 256, 256>>>(etyp);

    // tf32-round + K-permute all inputs in one launch
    k_cvtp3<<<4096, 256>>>(X,  xtf,  (size_t)NN * DIM / 16,
                           Wm, wmtf, (size_t)NT * DIM * DIM / 16,
                           Wu, wutf, (size_t)DIM * DIM2 / 16);

    dim3 gm(DIM / BN, (NE + BM - 1) / BM, NT);
    k_msg<<<gm, THREADS, SMEM_SZ>>>(bm, eidx);

    // round + permute aggregated messages in place before the update GEMM
    k_cvtp<<<4096, 256>>>(agg, agg, (size_t)NN * DIM / 16);

    dim3 gu(DIM / BN, (NN + BM - 1) / BM);
    k_upd<<<gu, THREADS, SMEM_SZ>>>(bu, out);

    k_ln<<<NN, 256>>>(out, X, gam, bet);
}